// round 7
// baseline (speedup 1.0000x reference)
#include <cuda_runtime.h>
#include <cstdint>

#define N_WRD  2000
#define B_SZ   64
#define CSZ    128
#define V_PIX  256
#define EMB    32

// ---------------- scratch (device globals; no allocations allowed) ----------
__device__ float    g_h0[B_SZ * 512];
__device__ float    g_wcode[B_SZ * 6000];
__device__ uint32_t g_vsu[V_PIX * EMB];                 // vs as tf32 bits
__device__ uint32_t g_e[(size_t)B_SZ * N_WRD * EMB];    // e as tf32 bits
__device__ float    g_act[B_SZ * N_WRD];
__device__ uint32_t g_w2tu[256 * 256];                  // fc2_w^T as tf32, [n][k]
__device__ uint32_t g_we2tu[64 * 256];                  // [fce|fca|0]^T tf32, [j][k]
__device__ uint32_t g_vcu[(size_t)B_SZ * CSZ * V_PIX];  // view_cell as tf32

// ============================ helpers =======================================
__device__ __forceinline__ uint32_t f2tf(float f) {
    uint32_t u; asm("cvt.rna.tf32.f32 %0, %1;" : "=r"(u) : "f"(f)); return u;
}
__device__ __forceinline__ void mma8(float* d, const uint32_t* a, const uint32_t* b) {
    asm volatile("mma.sync.aligned.m16n8k8.row.col.f32.tf32.tf32.f32 "
        "{%0,%1,%2,%3}, {%4,%5,%6,%7}, {%8,%9}, {%0,%1,%2,%3};"
        : "+f"(d[0]), "+f"(d[1]), "+f"(d[2]), "+f"(d[3])
        : "r"(a[0]), "r"(a[1]), "r"(a[2]), "r"(a[3]), "r"(b[0]), "r"(b[1]));
}
__device__ __forceinline__ void ldm_x4(uint32_t* r, uint32_t addr) {
    asm volatile("ldmatrix.sync.aligned.m8n8.x4.shared.b16 {%0,%1,%2,%3}, [%4];"
        : "=r"(r[0]), "=r"(r[1]), "=r"(r[2]), "=r"(r[3]) : "r"(addr));
}
__device__ __forceinline__ uint32_t smem_u32(const void* p) {
    uint32_t a;
    asm("{ .reg .u64 t; cvta.to.shared.u64 t, %1; cvt.u32.u64 %0, t; }"
        : "=r"(a) : "l"(p));
    return a;
}
#define CP_ASYNC16(dst, src) \
    asm volatile("cp.async.ca.shared.global [%0], [%1], 16;" :: "r"(dst), "l"(src))
#define CP_COMMIT() asm volatile("cp.async.commit_group;")
#define CP_WAIT1()  asm volatile("cp.async.wait_group 1;")
#define CP_WAIT0()  asm volatile("cp.async.wait_group 0;")
__device__ __forceinline__ float sigmoidf_(float x) {
    return 1.f / (1.f + __expf(-x));
}

// ====== setup kernel: weight transposes/converts + h0 + vs + VC convert =====
__global__ __launch_bounds__(256) void k_setup(
    const float* __restrict__ fc2_w, const float* __restrict__ fce_w,
    const float* __restrict__ fca_w, const float* __restrict__ vc_g,
    const float* __restrict__ v, const float* __restrict__ w2c_w1,
    const float* __restrict__ w2c_b1,
    const float* __restrict__ vse_w1, const float* __restrict__ vse_b1,
    const float* __restrict__ vse_w2, const float* __restrict__ vse_b2) {
    const int bid = blockIdx.x;
    const int t = threadIdx.x;
    if (bid < 256) {
        // W2T: block = k-row of fc2_w; coalesced read, scattered write
        int k = bid;
        g_w2tu[t * 256 + k] = f2tf(fc2_w[k * 256 + t]);
        if (bid < 64) {
            // We2T: block = j, thread = k
            int j = bid;
            float val = (j < 32) ? fce_w[t * 32 + j] : ((j == 32) ? fca_w[t] : 0.f);
            g_we2tu[j * 256 + t] = f2tf(val);
        }
    } else if (bid < 320) {
        int b = bid - 256;
#pragma unroll
        for (int half = 0; half < 2; half++) {
            int j = t + half * 256;
            float acc = w2c_b1[j];
#pragma unroll
            for (int i = 0; i < 7; i++)
                acc = fmaf(v[b * 7 + i], w2c_w1[i * 512 + j], acc);
            g_h0[b * 512 + j] = fmaxf(acc, 0.f);
        }
    } else if (bid < 352) {
        int vl = t >> 5, e = t & 31;
        int vv = (bid - 320) * 8 + vl;
        float x = -1.f + (2.f / 15.f) * (float)(vv >> 4);
        float y = -1.f + (2.f / 15.f) * (float)(vv & 15);
        float acc = vse_b2[e];
#pragma unroll 4
        for (int j = 0; j < 128; j++) {
            float h = fmaxf(fmaf(x, vse_w1[j], fmaf(y, vse_w1[128 + j], vse_b1[j])), 0.f);
            acc = fmaf(h, vse_w2[j * EMB + e], acc);
        }
        g_vsu[vv * EMB + e] = f2tf(acc);
    } else {
        // VC convert: 2048 blocks x 1024 elements
        size_t base = (size_t)(bid - 352) * 1024 + t * 4;
        float4 f = *(const float4*)&vc_g[base];
        uint4 u;
        u.x = f2tf(f.x); u.y = f2tf(f.y); u.z = f2tf(f.z); u.w = f2tf(f.w);
        *(uint4*)&g_vcu[base] = u;
    }
}

// ---------------- kernel 2: wcode = h0 @ w2 + b2 ----------------------------
__global__ __launch_bounds__(256) void k_wcode(const float* __restrict__ w2,
                                               const float* __restrict__ b2) {
    __shared__ float As[64 * 33];
    __shared__ float Bs[32 * 68];
    int t = threadIdx.x;
    int tx = t & 15, ty = t >> 4;
    int n0 = blockIdx.x * 64;
    float acc[4][4] = {};
    for (int k0 = 0; k0 < 512; k0 += 32) {
        for (int i = t; i < 2048; i += 256) {
            int r = i >> 5, k = i & 31;
            As[r * 33 + k] = g_h0[r * 512 + k0 + k];
        }
        for (int i = t; i < 2048; i += 256) {
            int k = i >> 6, n = i & 63;
            int nn = n0 + n;
            Bs[k * 68 + n] = (nn < 6000) ? w2[(k0 + k) * 6000 + nn] : 0.f;
        }
        __syncthreads();
#pragma unroll
        for (int k = 0; k < 32; k++) {
            float a[4], bb[4];
#pragma unroll
            for (int i = 0; i < 4; i++) a[i] = As[(4 * ty + i) * 33 + k];
#pragma unroll
            for (int j = 0; j < 4; j++) bb[j] = Bs[k * 68 + 4 * tx + j];
#pragma unroll
            for (int i = 0; i < 4; i++)
#pragma unroll
                for (int j = 0; j < 4; j++) acc[i][j] = fmaf(a[i], bb[j], acc[i][j]);
        }
        __syncthreads();
    }
#pragma unroll
    for (int i = 0; i < 4; i++) {
        int r = 4 * ty + i;
#pragma unroll
        for (int j = 0; j < 4; j++) {
            int col = n0 + 4 * tx + j;
            if (col < 6000) g_wcode[r * 6000 + col] = acc[i][j] + b2[col];
        }
    }
}

// ====== kernel A v2: 64-row tiles, 256 thr, 2 CTA/SM, ldmatrix, cp.async ====
// smem floats:
#define KA_AS    0          // A/H2 [64][260] = 16640
#define KA_BS    16640      // W2T dbuf 2x[256][20]=10240 ; later We2T chunk [64][132]=8448
#define KA_FC2B  26880      // 256
#define KA_FCEB  27136      // 32
#define KA_F1W   27168      // 768
#define KA_F1B   27936      // 256
#define KA_WC    28192      // 192
#define KA_TOT   28384      // -> 113536 bytes

__global__ __launch_bounds__(256, 2) void k_A(
    const float* __restrict__ fc1_w, const float* __restrict__ fc1_b,
    const float* __restrict__ fc2_b,
    const float* __restrict__ fca_b, const float* __restrict__ fce_b) {
    extern __shared__ float sm[];
    uint32_t* AsU  = (uint32_t*)sm;
    float*    fc2bS= sm + KA_FC2B;
    float*    fcebS= sm + KA_FCEB;
    float*    f1w  = sm + KA_F1W;
    float*    f1b  = sm + KA_F1B;
    float*    wcS  = sm + KA_WC;

    const uint32_t as_b = smem_u32(sm);
    const uint32_t bs_b = smem_u32(sm + KA_BS);

    const int t = threadIdx.x;
    const int wid = t >> 5, lane = t & 31;
    const int gr = lane >> 2, tg = lane & 3;
    const int lr8 = (lane >> 3) & 1, l7 = lane & 7, lhi = lane >> 4;
    const int row0 = blockIdx.x * 64;

    // stage consts
    for (int i = t; i < 768; i += 256) f1w[i] = fc1_w[i];
    f1b[t] = fc1_b[t];
    fc2bS[t] = fc2_b[t];
    if (t < 32) fcebS[t] = fce_b[t];
    if (t < 192) wcS[t] = g_wcode[row0 * 3 + t];

    // issue cp.async W2T chunks 0,1 ([256 n][16 k] each, stride 20)
#pragma unroll
    for (int c = 0; c < 2; c++) {
#pragma unroll
        for (int q = 0; q < 4; q++) {
            int s = t + 256 * q;
            int n = s >> 2, kq = s & 3;
            uint32_t dst = bs_b + (uint32_t)((c * 5120 + n * 20 + kq * 4) * 4);
            CP_ASYNC16(dst, &g_w2tu[n * 256 + c * 16 + kq * 4]);
        }
        CP_COMMIT();
    }
    __syncthreads();

    // ---- fc1 -> As tf32 ----
    {
        int r = t >> 2, kb = (t & 3) * 64;
        float w0 = wcS[r * 3 + 0], w1 = wcS[r * 3 + 1], w2 = wcS[r * 3 + 2];
        for (int j = 0; j < 64; j += 4) {
            uint4 u;
            int k = kb + j;
            u.x = f2tf(fmaxf(fmaf(w0, f1w[k+0], fmaf(w1, f1w[256+k+0], fmaf(w2, f1w[512+k+0], f1b[k+0]))), 0.f));
            u.y = f2tf(fmaxf(fmaf(w0, f1w[k+1], fmaf(w1, f1w[256+k+1], fmaf(w2, f1w[512+k+1], f1b[k+1]))), 0.f));
            u.z = f2tf(fmaxf(fmaf(w0, f1w[k+2], fmaf(w1, f1w[256+k+2], fmaf(w2, f1w[512+k+2], f1b[k+2]))), 0.f));
            u.w = f2tf(fmaxf(fmaf(w0, f1w[k+3], fmaf(w1, f1w[256+k+3], fmaf(w2, f1w[512+k+3], f1b[k+3]))), 0.f));
            *(uint4*)&AsU[r * 260 + k] = u;
        }
    }
    CP_WAIT1();
    __syncthreads();

    // ---- MMA1: H2raw = A @ W2 (64x256, K=256). warps: 2m x 4n --------------
    const int wm = wid & 1, wn = wid >> 1;
    const int m0 = wm * 32, n0 = wn * 64;
    float acc1[2][8][4] = {};
    for (int kc = 0; kc < 16; kc++) {
        const uint32_t buf = bs_b + (uint32_t)((kc & 1) * 5120 * 4);
#pragma unroll
        for (int ks2 = 0; ks2 < 2; ks2++) {
            uint32_t aF[2][4];
#pragma unroll
            for (int mt = 0; mt < 2; mt++) {
                uint32_t adr = as_b + (uint32_t)(((m0 + mt * 16 + lr8 * 8 + l7) * 260
                                                  + kc * 16 + ks2 * 8 + lhi * 4) * 4);
                ldm_x4(aF[mt], adr);
            }
#pragma unroll
            for (int ntp = 0; ntp < 4; ntp++) {
                uint32_t bF[4];
                uint32_t adr = buf + (uint32_t)(((n0 + (ntp * 2 + lhi) * 8 + l7) * 20
                                                 + ks2 * 8 + lr8 * 4) * 4);
                ldm_x4(bF, adr);
#pragma unroll
                for (int mt = 0; mt < 2; mt++) {
                    mma8(acc1[mt][2 * ntp],     aF[mt], bF);
                    mma8(acc1[mt][2 * ntp + 1], aF[mt], bF + 2);
                }
            }
        }
        if (kc < 14) {
            __syncthreads();
            int cn = kc + 2;
#pragma unroll
            for (int q = 0; q < 4; q++) {
                int s = t + 256 * q;
                int n = s >> 2, kq = s & 3;
                uint32_t dst = bs_b + (uint32_t)(((cn & 1) * 5120 + n * 20 + kq * 4) * 4);
                CP_ASYNC16(dst, &g_w2tu[n * 256 + cn * 16 + kq * 4]);
            }
            CP_COMMIT();
        }
        if (kc < 15) {
            if (kc == 14) { CP_WAIT0(); } else { CP_WAIT1(); }
            __syncthreads();
        }
    }
    __syncthreads();   // all warps finished MMA1 reads of As and Bs

    // issue We2T chunk 0 ([64 j][128 k], stride 132) while epilogue computes
#pragma unroll
    for (int q = 0; q < 8; q++) {
        int s = t + 256 * q;
        int j = s >> 5, kq = s & 31;
        uint32_t dst = bs_b + (uint32_t)((j * 132 + kq * 4) * 4);
        CP_ASYNC16(dst, &g_we2tu[j * 256 + kq * 4]);
    }
    CP_COMMIT();

    // ---- epilogue1: H2 = relu(acc + bias) -> As tf32 -----------------------
#pragma unroll
    for (int mt = 0; mt < 2; mt++) {
#pragma unroll
        for (int nt = 0; nt < 8; nt++) {
            int col = n0 + nt * 8 + 2 * tg;
            int r0 = m0 + mt * 16 + gr;
            float b0 = fc2bS[col], b1 = fc2bS[col + 1];
            float* d = acc1[mt][nt];
            uint2 u0, u1;
            u0.x = f2tf(fmaxf(d[0] + b0, 0.f));
            u0.y = f2tf(fmaxf(d[1] + b1, 0.f));
            u1.x = f2tf(fmaxf(d[2] + b0, 0.f));
            u1.y = f2tf(fmaxf(d[3] + b1, 0.f));
            *(uint2*)&AsU[r0 * 260 + col]       = u0;
            *(uint2*)&AsU[(r0 + 8) * 260 + col] = u1;
        }
    }
    CP_WAIT0();
    __syncthreads();

    // ---- MMA2: D2 = H2 @ We2 (64x64, K=256 in 2 chunks). j-tile 16/warp ----
    const int j0 = wn * 16;
    float acc2[2][2][4] = {};
#pragma unroll
    for (int ks = 0; ks < 16; ks++) {
        uint32_t aF[2][4];
#pragma unroll
        for (int mt = 0; mt < 2; mt++) {
            uint32_t adr = as_b + (uint32_t)(((m0 + mt * 16 + lr8 * 8 + l7) * 260
                                              + ks * 8 + lhi * 4) * 4);
            ldm_x4(aF[mt], adr);
        }
        uint32_t bF[4];
        uint32_t adr = bs_b + (uint32_t)(((j0 + lhi * 8 + l7) * 132 + ks * 8 + lr8 * 4) * 4);
        ldm_x4(bF, adr);
#pragma unroll
        for (int mt = 0; mt < 2; mt++) {
            mma8(acc2[mt][0], aF[mt], bF);
            mma8(acc2[mt][1], aF[mt], bF + 2);
        }
    }
    __syncthreads();
    // We2T chunk 1 (k 128..255)
#pragma unroll
    for (int q = 0; q < 8; q++) {
        int s = t + 256 * q;
        int j = s >> 5, kq = s & 31;
        uint32_t dst = bs_b + (uint32_t)((j * 132 + kq * 4) * 4);
        CP_ASYNC16(dst, &g_we2tu[j * 256 + 128 + kq * 4]);
    }
    CP_COMMIT();
    CP_WAIT0();
    __syncthreads();
#pragma unroll
    for (int ks = 16; ks < 32; ks++) {
        uint32_t aF[2][4];
#pragma unroll
        for (int mt = 0; mt < 2; mt++) {
            uint32_t adr = as_b + (uint32_t)(((m0 + mt * 16 + lr8 * 8 + l7) * 260
                                              + ks * 8 + lhi * 4) * 4);
            ldm_x4(aF[mt], adr);
        }
        uint32_t bF[4];
        uint32_t adr = bs_b + (uint32_t)(((j0 + lhi * 8 + l7) * 132 + (ks - 16) * 8 + lr8 * 4) * 4);
        ldm_x4(bF, adr);
#pragma unroll
        for (int mt = 0; mt < 2; mt++) {
            mma8(acc2[mt][0], aF[mt], bF);
            mma8(acc2[mt][1], aF[mt], bF + 2);
        }
    }

    // ---- epilogue2: e (tf32 bits) + act --------------------------------------
    const float fcab = fca_b[0];
#pragma unroll
    for (int mt = 0; mt < 2; mt++) {
        int r0 = m0 + mt * 16 + gr;
#pragma unroll
        for (int ntp = 0; ntp < 2; ntp++) {
            int col = j0 + ntp * 8 + 2 * tg;
            float* d = acc2[mt][ntp];
            if (col < 32) {
                float b0 = fcebS[col], b1 = fcebS[col + 1];
                uint2 u0, u1;
                u0.x = f2tf(d[0] + b0); u0.y = f2tf(d[1] + b1);
                u1.x = f2tf(d[2] + b0); u1.y = f2tf(d[3] + b1);
                *(uint2*)&g_e[(size_t)(row0 + r0) * 32 + col]     = u0;
                *(uint2*)&g_e[(size_t)(row0 + r0 + 8) * 32 + col] = u1;
            } else if (col == 32) {
                g_act[row0 + r0]     = sigmoidf_(d[0] + fcab);
                g_act[row0 + r0 + 8] = sigmoidf_(d[2] + fcab);
            }
        }
    }
}

// ======== kernel B: relation -> reg softmax -> route -> out GEMM ===========
#define KB_RT    0          // route [64 n][260 v] = 16640
#define KB_UN    16640      // union: vsS[256][36]=9216 @+0, es[64][36]=2304 @+9216
                            //        later: vc buf0 @+0 (4608), buf1 @+4608
#define KB_ACT   28160      // 64
#define KB_RM    28224      // 64*4
#define KB_RS    28480      // 64*4
#define KB_TOT   28736      // -> 114944 bytes

__global__ __launch_bounds__(256, 2) void k_B(float* __restrict__ out) {
    extern __shared__ float sm[];
    float*    rtF  = sm + KB_RT;
    uint32_t* rtU  = (uint32_t*)rtF;
    uint32_t* vsU  = (uint32_t*)(sm + KB_UN);
    uint32_t* esU  = (uint32_t*)(sm + KB_UN + 9216);
    float*    actS = sm + KB_ACT;
    float*    redm = sm + KB_RM;
    float*    reds = sm + KB_RS;

    const uint32_t rt_b = smem_u32(rtF);
    const uint32_t un_b = smem_u32(sm + KB_UN);
    const uint32_t es_b = un_b + 9216 * 4;

    const int t = threadIdx.x;
    const int wid = t >> 5, lane = t & 31;
    const int gr = lane >> 2, tg = lane & 3;
    const int lr8 = (lane >> 3) & 1, l7 = lane & 7, lhi = lane >> 4;
    const int n0g = blockIdx.x * 64;
    const int b   = blockIdx.y;
    const uint32_t* Avcu = g_vcu + (size_t)b * CSZ * V_PIX;

    for (int i = t; i < 8192; i += 256) {
        int v = i >> 5, e = i & 31;
        vsU[v * 36 + e] = g_vsu[i];
    }
    for (int i = t; i < 2048; i += 256) {
        int n = i >> 5, j = i & 31;
        int row = n0g + n;
        esU[n * 36 + j] = (row < N_WRD) ? g_e[(size_t)(b * N_WRD + row) * 32 + j] : 0u;
    }
    if (t < 64) {
        int row = n0g + t;
        actS[t] = (row < N_WRD) ? g_act[b * N_WRD + row] : 0.f;
    }
    __syncthreads();

    const int wm = wid & 1, wn = wid >> 1;
    const int m0 = wm * 32, v0 = wn * 64;
    float accr[2][8][4] = {};
#pragma unroll
    for (int ks = 0; ks < 4; ks++) {
        uint32_t aF[2][4];
#pragma unroll
        for (int mt = 0; mt < 2; mt++) {
            uint32_t adr = es_b + (uint32_t)(((m0 + mt * 16 + lr8 * 8 + l7) * 36
                                              + ks * 8 + lhi * 4) * 4);
            ldm_x4(aF[mt], adr);
        }
#pragma unroll
        for (int ntp = 0; ntp < 4; ntp++) {
            uint32_t bF[4];
            uint32_t adr = un_b + (uint32_t)(((v0 + (ntp * 2 + lhi) * 8 + l7) * 36
                                              + ks * 8 + lr8 * 4) * 4);
            ldm_x4(bF, adr);
#pragma unroll
            for (int mt = 0; mt < 2; mt++) {
                mma8(accr[mt][2 * ntp],     aF[mt], bF);
                mma8(accr[mt][2 * ntp + 1], aF[mt], bF + 2);
            }
        }
    }

#pragma unroll
    for (int mt = 0; mt < 2; mt++) {
        float mxa = -1e30f, mxb = -1e30f;
#pragma unroll
        for (int nt = 0; nt < 8; nt++) {
            float* d = accr[mt][nt];
            mxa = fmaxf(mxa, fmaxf(d[0], d[1]));
            mxb = fmaxf(mxb, fmaxf(d[2], d[3]));
        }
        mxa = fmaxf(mxa, __shfl_xor_sync(0xffffffffu, mxa, 1));
        mxa = fmaxf(mxa, __shfl_xor_sync(0xffffffffu, mxa, 2));
        mxb = fmaxf(mxb, __shfl_xor_sync(0xffffffffu, mxb, 1));
        mxb = fmaxf(mxb, __shfl_xor_sync(0xffffffffu, mxb, 2));
        if (tg == 0) {
            redm[(m0 + mt * 16 + gr) * 4 + wn] = mxa;
            redm[(m0 + mt * 16 + 8 + gr) * 4 + wn] = mxb;
        }
    }
    __syncthreads();

#pragma unroll
    for (int c = 0; c < 2; c++) {
#pragma unroll
        for (int q = 0; q < 4; q++) {
            int s = t + 256 * q;
            int row = s >> 3, k4 = s & 7;
            uint32_t dst = un_b + (uint32_t)((c * 4608 + row * 36 + k4 * 4) * 4);
            CP_ASYNC16(dst, Avcu + row * 256 + c * 32 + k4 * 4);
        }
        CP_COMMIT();
    }

#pragma unroll
    for (int mt = 0; mt < 2; mt++) {
        int na = m0 + mt * 16 + gr, nb = na + 8;
        float ma = fmaxf(fmaxf(redm[na * 4 + 0], redm[na * 4 + 1]),
                         fmaxf(redm[na * 4 + 2], redm[na * 4 + 3]));
        float mb = fmaxf(fmaxf(redm[nb * 4 + 0], redm[nb * 4 + 1]),
                         fmaxf(redm[nb * 4 + 2], redm[nb * 4 + 3]));
        float sa = 0.f, sb = 0.f;
#pragma unroll
        for (int nt = 0; nt < 8; nt++) {
            float* d = accr[mt][nt];
            d[0] = __expf(d[0] - ma); d[1] = __expf(d[1] - ma);
            d[2] = __expf(d[2] - mb); d[3] = __expf(d[3] - mb);
            sa += d[0] + d[1];
            sb += d[2] + d[3];
        }
        sa += __shfl_xor_sync(0xffffffffu, sa, 1);
        sa += __shfl_xor_sync(0xffffffffu, sa, 2);
        sb += __shfl_xor_sync(0xffffffffu, sb, 1);
        sb += __shfl_xor_sync(0xffffffffu, sb, 2);
        if (tg == 0) { reds[na * 4 + wn] = sa; reds[nb * 4 + wn] = sb; }
    }
    __syncthreads();

#pragma unroll
    for (int mt = 0; mt < 2; mt++) {
        int na = m0 + mt * 16 + gr, nb = na + 8;
        float sA = reds[na * 4 + 0] + reds[na * 4 + 1] + reds[na * 4 + 2] + reds[na * 4 + 3];
        float sB = reds[nb * 4 + 0] + reds[nb * 4 + 1] + reds[nb * 4 + 2] + reds[nb * 4 + 3];
        float scA = actS[na] / sA;
        float scB = actS[nb] / sB;
#pragma unroll
        for (int nt = 0; nt < 8; nt++) {
            int v = v0 + nt * 8 + 2 * tg;
            float* d = accr[mt][nt];
            uint2 ua, ub;
            ua.x = f2tf(d[0] * scA); ua.y = f2tf(d[1] * scA);
            ub.x = f2tf(d[2] * scB); ub.y = f2tf(d[3] * scB);
            *(uint2*)&rtU[na * 260 + v] = ua;
            *(uint2*)&rtU[nb * 260 + v] = ub;
        }
    }
    __syncthreads();

    const int wm2 = wid >> 1, wn2 = wid & 1;
    const int c0 = wm2 * 32, n0o = wn2 * 32;
    float acco[2][4][4] = {};
    for (int c = 0; c < 8; c++) {
        if (c < 7) { CP_WAIT1(); } else { CP_WAIT0(); }
        __syncthreads();
        const uint32_t vcb = un_b + (uint32_t)((c & 1) * 4608 * 4);
#pragma unroll
        for (int ks = 0; ks < 4; ks++) {
            uint32_t aF[2][4];
#pragma unroll
            for (int mt = 0; mt < 2; mt++) {
                uint32_t adr = vcb + (uint32_t)(((c0 + mt * 16 + lr8 * 8 + l7) * 36
                                                 + ks * 8 + lhi * 4) * 4);
                ldm_x4(aF[mt], adr);
            }
#pragma unroll
            for (int ntp = 0; ntp < 2; ntp++) {
                uint32_t bF[4];
                uint32_t adr = rt_b + (uint32_t)(((n0o + (ntp * 2 + lhi) * 8 + l7) * 260
                                                  + c * 32 + ks * 8 + lr8 * 4) * 4);
                ldm_x4(bF, adr);
#pragma unroll
                for (int mt = 0; mt < 2; mt++) {
                    mma8(acco[mt][2 * ntp],     aF[mt], bF);
                    mma8(acco[mt][2 * ntp + 1], aF[mt], bF + 2);
                }
            }
        }
        if (c < 6) {
            __syncthreads();
            int cn = c + 2;
#pragma unroll
            for (int q = 0; q < 4; q++) {
                int s = t + 256 * q;
                int row = s >> 3, k4 = s & 7;
                uint32_t dst = un_b + (uint32_t)(((cn & 1) * 4608 + row * 36 + k4 * 4) * 4);
                CP_ASYNC16(dst, Avcu + row * 256 + cn * 32 + k4 * 4);
            }
            CP_COMMIT();
        }
    }

#pragma unroll
    for (int mt = 0; mt < 2; mt++) {
#pragma unroll
        for (int nt = 0; nt < 4; nt++) {
            int r0 = c0 + mt * 16 + gr;
            int ng = n0g + n0o + nt * 8 + 2 * tg;
            float* d = acco[mt][nt];
            if (ng < N_WRD) {
                float2 s0; s0.x = d[0]; s0.y = d[1];
                float2 s1; s1.x = d[2]; s1.y = d[3];
                *(float2*)&out[((size_t)b * CSZ + r0) * N_WRD + ng]     = s0;
                *(float2*)&out[((size_t)b * CSZ + r0 + 8) * N_WRD + ng] = s1;
            }
        }
    }
}

// ---------------- launch --------------------------------------------------
extern "C" void kernel_launch(void* const* d_in, const int* in_sizes, int n_in,
                              void* d_out, int out_size) {
    const float* view_cell = (const float*)d_in[0];
    const float* v         = (const float*)d_in[1];
    const float* w2c_w1    = (const float*)d_in[2];
    const float* w2c_b1    = (const float*)d_in[3];
    const float* w2c_w2    = (const float*)d_in[4];
    const float* w2c_b2    = (const float*)d_in[5];
    const float* fc1_w     = (const float*)d_in[6];
    const float* fc1_b     = (const float*)d_in[7];
    const float* fc2_w     = (const float*)d_in[8];
    const float* fc2_b     = (const float*)d_in[9];
    const float* fca_w     = (const float*)d_in[10];
    const float* fca_b     = (const float*)d_in[11];
    const float* fce_w     = (const float*)d_in[12];
    const float* fce_b     = (const float*)d_in[13];
    const float* vse_w1    = (const float*)d_in[14];
    const float* vse_b1    = (const float*)d_in[15];
    const float* vse_w2    = (const float*)d_in[16];
    const float* vse_b2    = (const float*)d_in[17];
    float* out = (float*)d_out;

    static bool attr_set = false;
    if (!attr_set) {
        cudaFuncSetAttribute(k_A, cudaFuncAttributeMaxDynamicSharedMemorySize, KA_TOT * 4);
        cudaFuncSetAttribute(k_B, cudaFuncAttributeMaxDynamicSharedMemorySize, KB_TOT * 4);
        attr_set = true;
    }

    k_setup<<<352 + 2048, 256>>>(fc2_w, fce_w, fca_w, view_cell, v, w2c_w1, w2c_b1,
                                 vse_w1, vse_b1, vse_w2, vse_b2);
    k_wcode<<<(6000 + 63) / 64, 256>>>(w2c_w2, w2c_b2);
    k_A<<<(B_SZ * N_WRD) / 64, 256, KA_TOT * 4>>>(fc1_w, fc1_b, fc2_b, fca_b, fce_b);
    dim3 gridB((N_WRD + 63) / 64, B_SZ);
    k_B<<<gridB, 256, KB_TOT * 4>>>(out);
}

// round 8
// speedup vs baseline: 1.0746x; 1.0746x over previous
#include <cuda_runtime.h>
#include <cstdint>

#define N_WRD  2000
#define B_SZ   64
#define CSZ    128
#define V_PIX  256
#define EMB    32

// ---------------- scratch (device globals; no allocations allowed) ----------
__device__ float    g_h0[B_SZ * 512];
__device__ float    g_wcode[B_SZ * 6000 + 192];         // padded for tile overrun
__device__ uint32_t g_vsu[V_PIX * EMB];                 // vs as tf32 bits
__device__ uint32_t g_w2tu[256 * 256];                  // fc2_w^T as tf32, [n][k]
__device__ uint32_t g_we2tu[64 * 256];                  // [fce|fca|0]^T tf32, [j][k]
__device__ uint32_t g_vcu[(size_t)B_SZ * CSZ * V_PIX];  // view_cell as tf32

// ============================ helpers =======================================
__device__ __forceinline__ uint32_t f2tf(float f) {
    uint32_t u; asm("cvt.rna.tf32.f32 %0, %1;" : "=r"(u) : "f"(f)); return u;
}
__device__ __forceinline__ void mma8(float* d, const uint32_t* a, const uint32_t* b) {
    asm volatile("mma.sync.aligned.m16n8k8.row.col.f32.tf32.tf32.f32 "
        "{%0,%1,%2,%3}, {%4,%5,%6,%7}, {%8,%9}, {%0,%1,%2,%3};"
        : "+f"(d[0]), "+f"(d[1]), "+f"(d[2]), "+f"(d[3])
        : "r"(a[0]), "r"(a[1]), "r"(a[2]), "r"(a[3]), "r"(b[0]), "r"(b[1]));
}
__device__ __forceinline__ void ldm_x4(uint32_t* r, uint32_t addr) {
    asm volatile("ldmatrix.sync.aligned.m8n8.x4.shared.b16 {%0,%1,%2,%3}, [%4];"
        : "=r"(r[0]), "=r"(r[1]), "=r"(r[2]), "=r"(r[3]) : "r"(addr));
}
__device__ __forceinline__ uint32_t smem_u32(const void* p) {
    uint32_t a;
    asm("{ .reg .u64 t; cvta.to.shared.u64 t, %1; cvt.u32.u64 %0, t; }"
        : "=r"(a) : "l"(p));
    return a;
}
#define CP_ASYNC16(dst, src) \
    asm volatile("cp.async.ca.shared.global [%0], [%1], 16;" :: "r"(dst), "l"(src))
#define CP_COMMIT() asm volatile("cp.async.commit_group;")
#define CP_WAIT1()  asm volatile("cp.async.wait_group 1;")
#define CP_WAIT0()  asm volatile("cp.async.wait_group 0;")
__device__ __forceinline__ float sigmoidf_(float x) {
    return 1.f / (1.f + __expf(-x));
}

// ====== setup kernel: weight transposes/converts + h0 + vs + VC convert =====
__global__ __launch_bounds__(256) void k_setup(
    const float* __restrict__ fc2_w, const float* __restrict__ fce_w,
    const float* __restrict__ fca_w, const float* __restrict__ vc_g,
    const float* __restrict__ v, const float* __restrict__ w2c_w1,
    const float* __restrict__ w2c_b1,
    const float* __restrict__ vse_w1, const float* __restrict__ vse_b1,
    const float* __restrict__ vse_w2, const float* __restrict__ vse_b2) {
    const int bid = blockIdx.x;
    const int t = threadIdx.x;
    if (bid < 256) {
        int k = bid;
        g_w2tu[t * 256 + k] = f2tf(fc2_w[k * 256 + t]);
        if (bid < 64) {
            int j = bid;
            float val = (j < 32) ? fce_w[t * 32 + j] : ((j == 32) ? fca_w[t] : 0.f);
            g_we2tu[j * 256 + t] = f2tf(val);
        }
    } else if (bid < 320) {
        int b = bid - 256;
#pragma unroll
        for (int half = 0; half < 2; half++) {
            int j = t + half * 256;
            float acc = w2c_b1[j];
#pragma unroll
            for (int i = 0; i < 7; i++)
                acc = fmaf(v[b * 7 + i], w2c_w1[i * 512 + j], acc);
            g_h0[b * 512 + j] = fmaxf(acc, 0.f);
        }
    } else if (bid < 352) {
        int vl = t >> 5, e = t & 31;
        int vv = (bid - 320) * 8 + vl;
        float x = -1.f + (2.f / 15.f) * (float)(vv >> 4);
        float y = -1.f + (2.f / 15.f) * (float)(vv & 15);
        float acc = vse_b2[e];
#pragma unroll 4
        for (int j = 0; j < 128; j++) {
            float h = fmaxf(fmaf(x, vse_w1[j], fmaf(y, vse_w1[128 + j], vse_b1[j])), 0.f);
            acc = fmaf(h, vse_w2[j * EMB + e], acc);
        }
        g_vsu[vv * EMB + e] = f2tf(acc);
    } else {
        size_t base = (size_t)(bid - 352) * 1024 + t * 4;
        float4 f = *(const float4*)&vc_g[base];
        uint4 u;
        u.x = f2tf(f.x); u.y = f2tf(f.y); u.z = f2tf(f.z); u.w = f2tf(f.w);
        *(uint4*)&g_vcu[base] = u;
    }
}

// ---------------- kernel 2: wcode = h0 @ w2 + b2 ----------------------------
__global__ __launch_bounds__(256) void k_wcode(const float* __restrict__ w2,
                                               const float* __restrict__ b2) {
    __shared__ float As[64 * 33];
    __shared__ float Bs[32 * 68];
    int t = threadIdx.x;
    int tx = t & 15, ty = t >> 4;
    int n0 = blockIdx.x * 64;
    float acc[4][4] = {};
    for (int k0 = 0; k0 < 512; k0 += 32) {
        for (int i = t; i < 2048; i += 256) {
            int r = i >> 5, k = i & 31;
            As[r * 33 + k] = g_h0[r * 512 + k0 + k];
        }
        for (int i = t; i < 2048; i += 256) {
            int k = i >> 6, n = i & 63;
            int nn = n0 + n;
            Bs[k * 68 + n] = (nn < 6000) ? w2[(k0 + k) * 6000 + nn] : 0.f;
        }
        __syncthreads();
#pragma unroll
        for (int k = 0; k < 32; k++) {
            float a[4], bb[4];
#pragma unroll
            for (int i = 0; i < 4; i++) a[i] = As[(4 * ty + i) * 33 + k];
#pragma unroll
            for (int j = 0; j < 4; j++) bb[j] = Bs[k * 68 + 4 * tx + j];
#pragma unroll
            for (int i = 0; i < 4; i++)
#pragma unroll
                for (int j = 0; j < 4; j++) acc[i][j] = fmaf(a[i], bb[j], acc[i][j]);
        }
        __syncthreads();
    }
#pragma unroll
    for (int i = 0; i < 4; i++) {
        int r = 4 * ty + i;
#pragma unroll
        for (int j = 0; j < 4; j++) {
            int col = n0 + 4 * tx + j;
            if (col < 6000) g_wcode[r * 6000 + col] = acc[i][j] + b2[col];
        }
    }
}

// ====== fused kernel: fc1 -> fc2 -> fce/fca -> relation -> softmax -> out ===
// smem floats:
#define KF_AS    0          // As [64][260]=16640: A -> H2 -> es([64][36]) -> route
#define KF_BUF   16640      // 10240: W2T dbuf 2x5120 / We2T 8448 / vs 9216 / VC dbuf 9216
#define KF_ACT   26880      // 64
#define KF_RM    26944      // 256
#define KF_RS    27200      // 256
#define KF_FC2B  27456      // 256
#define KF_FCEB  27712      // 32
#define KF_WC    27744      // 192
#define KF_TOT   27936      // -> 111744 bytes

__global__ __launch_bounds__(256, 2) void k_AB(
    const float* __restrict__ fc1_w, const float* __restrict__ fc1_b,
    const float* __restrict__ fc2_b,
    const float* __restrict__ fca_b, const float* __restrict__ fce_b,
    float* __restrict__ out) {
    extern __shared__ float sm[];
    uint32_t* AsU  = (uint32_t*)sm;
    float*    actS = sm + KF_ACT;
    float*    redm = sm + KF_RM;
    float*    reds = sm + KF_RS;
    float*    fc2bS= sm + KF_FC2B;
    float*    fcebS= sm + KF_FCEB;
    float*    wcS  = sm + KF_WC;

    const uint32_t as_b  = smem_u32(sm);
    const uint32_t buf_b = smem_u32(sm + KF_BUF);

    const int t = threadIdx.x;
    const int wid = t >> 5, lane = t & 31;
    const int gr = lane >> 2, tg = lane & 3;
    const int lr8 = (lane >> 3) & 1, l7 = lane & 7, lhi = lane >> 4;
    const int n0g = blockIdx.x * 64;       // word tile within batch
    const int b   = blockIdx.y;
    const int row0g = b * N_WRD + n0g;     // global word row

    // ---- consts + wcode rows ----
    fc2bS[t] = fc2_b[t];
    if (t < 32) fcebS[t] = fce_b[t];
    if (t < 192) wcS[t] = g_wcode[row0g * 3 + t];

    // preload W2T chunks 0,1 ([256 n][16 k], stride 20)
#pragma unroll
    for (int c = 0; c < 2; c++) {
#pragma unroll
        for (int q = 0; q < 4; q++) {
            int s = t + 256 * q;
            int n = s >> 2, kq = s & 3;
            uint32_t dst = buf_b + (uint32_t)((c * 5120 + n * 20 + kq * 4) * 4);
            CP_ASYNC16(dst, &g_w2tu[n * 256 + c * 16 + kq * 4]);
        }
        CP_COMMIT();
    }
    __syncthreads();

    // ---- fc1 -> As tf32 (weights straight from global, L1-cached) ----
    {
        int r = t >> 2, kb = (t & 3) * 64;
        float w0 = wcS[r * 3 + 0], w1 = wcS[r * 3 + 1], w2 = wcS[r * 3 + 2];
        for (int j = 0; j < 64; j += 4) {
            uint4 u;
            int k = kb + j;
            u.x = f2tf(fmaxf(fmaf(w0, fc1_w[k+0], fmaf(w1, fc1_w[256+k+0], fmaf(w2, fc1_w[512+k+0], fc1_b[k+0]))), 0.f));
            u.y = f2tf(fmaxf(fmaf(w0, fc1_w[k+1], fmaf(w1, fc1_w[256+k+1], fmaf(w2, fc1_w[512+k+1], fc1_b[k+1]))), 0.f));
            u.z = f2tf(fmaxf(fmaf(w0, fc1_w[k+2], fmaf(w1, fc1_w[256+k+2], fmaf(w2, fc1_w[512+k+2], fc1_b[k+2]))), 0.f));
            u.w = f2tf(fmaxf(fmaf(w0, fc1_w[k+3], fmaf(w1, fc1_w[256+k+3], fmaf(w2, fc1_w[512+k+3], fc1_b[k+3]))), 0.f));
            *(uint4*)&AsU[r * 260 + k] = u;
        }
    }
    CP_WAIT1();
    __syncthreads();

    // ---- MMA1: H2raw = A @ W2 (64x256, K=256). warps: 2m x 4n --------------
    const int wm = wid & 1, wn = wid >> 1;
    const int m0 = wm * 32, n0 = wn * 64;
    {
        float acc1[2][8][4] = {};
        for (int kc = 0; kc < 16; kc++) {
            const uint32_t buf = buf_b + (uint32_t)((kc & 1) * 5120 * 4);
#pragma unroll
            for (int ks2 = 0; ks2 < 2; ks2++) {
                uint32_t aF[2][4];
#pragma unroll
                for (int mt = 0; mt < 2; mt++) {
                    uint32_t adr = as_b + (uint32_t)(((m0 + mt * 16 + lr8 * 8 + l7) * 260
                                                      + kc * 16 + ks2 * 8 + lhi * 4) * 4);
                    ldm_x4(aF[mt], adr);
                }
#pragma unroll
                for (int ntp = 0; ntp < 4; ntp++) {
                    uint32_t bF[4];
                    uint32_t adr = buf + (uint32_t)(((n0 + (ntp * 2 + lhi) * 8 + l7) * 20
                                                     + ks2 * 8 + lr8 * 4) * 4);
                    ldm_x4(bF, adr);
#pragma unroll
                    for (int mt = 0; mt < 2; mt++) {
                        mma8(acc1[mt][2 * ntp],     aF[mt], bF);
                        mma8(acc1[mt][2 * ntp + 1], aF[mt], bF + 2);
                    }
                }
            }
            if (kc < 14) {
                __syncthreads();
                int cn = kc + 2;
#pragma unroll
                for (int q = 0; q < 4; q++) {
                    int s = t + 256 * q;
                    int n = s >> 2, kq = s & 3;
                    uint32_t dst = buf_b + (uint32_t)(((cn & 1) * 5120 + n * 20 + kq * 4) * 4);
                    CP_ASYNC16(dst, &g_w2tu[n * 256 + cn * 16 + kq * 4]);
                }
                CP_COMMIT();
            }
            if (kc < 15) {
                if (kc == 14) { CP_WAIT0(); } else { CP_WAIT1(); }
                __syncthreads();
            }
        }
        __syncthreads();   // all warps finished MMA1 reads

        // issue We2T chunk 0 ([64 j][128 k], stride 132)
#pragma unroll
        for (int q = 0; q < 8; q++) {
            int s = t + 256 * q;
            int j = s >> 5, kq = s & 31;
            uint32_t dst = buf_b + (uint32_t)((j * 132 + kq * 4) * 4);
            CP_ASYNC16(dst, &g_we2tu[j * 256 + kq * 4]);
        }
        CP_COMMIT();

        // epilogue1: H2 = relu(acc + bias) -> As tf32
#pragma unroll
        for (int mt = 0; mt < 2; mt++) {
#pragma unroll
            for (int nt = 0; nt < 8; nt++) {
                int col = n0 + nt * 8 + 2 * tg;
                int r0 = m0 + mt * 16 + gr;
                float b0 = fc2bS[col], b1 = fc2bS[col + 1];
                float* d = acc1[mt][nt];
                uint2 u0, u1;
                u0.x = f2tf(fmaxf(d[0] + b0, 0.f));
                u0.y = f2tf(fmaxf(d[1] + b1, 0.f));
                u1.x = f2tf(fmaxf(d[2] + b0, 0.f));
                u1.y = f2tf(fmaxf(d[3] + b1, 0.f));
                *(uint2*)&AsU[r0 * 260 + col]       = u0;
                *(uint2*)&AsU[(r0 + 8) * 260 + col] = u1;
            }
        }
    }
    CP_WAIT0();
    __syncthreads();

    // ---- MMA2: D2 = H2 @ We2 (64x64, K=256 in 2 halves) --------------------
    const int j0 = wn * 16;
    float acc2[2][2][4] = {};
#pragma unroll
    for (int ks = 0; ks < 16; ks++) {
        uint32_t aF[2][4];
#pragma unroll
        for (int mt = 0; mt < 2; mt++) {
            uint32_t adr = as_b + (uint32_t)(((m0 + mt * 16 + lr8 * 8 + l7) * 260
                                              + ks * 8 + lhi * 4) * 4);
            ldm_x4(aF[mt], adr);
        }
        uint32_t bF[4];
        uint32_t adr = buf_b + (uint32_t)(((j0 + lhi * 8 + l7) * 132 + ks * 8 + lr8 * 4) * 4);
        ldm_x4(bF, adr);
#pragma unroll
        for (int mt = 0; mt < 2; mt++) {
            mma8(acc2[mt][0], aF[mt], bF);
            mma8(acc2[mt][1], aF[mt], bF + 2);
        }
    }
    __syncthreads();
#pragma unroll
    for (int q = 0; q < 8; q++) {
        int s = t + 256 * q;
        int j = s >> 5, kq = s & 31;
        uint32_t dst = buf_b + (uint32_t)((j * 132 + kq * 4) * 4);
        CP_ASYNC16(dst, &g_we2tu[j * 256 + 128 + kq * 4]);
    }
    CP_COMMIT();
    CP_WAIT0();
    __syncthreads();
#pragma unroll
    for (int ks = 16; ks < 32; ks++) {
        uint32_t aF[2][4];
#pragma unroll
        for (int mt = 0; mt < 2; mt++) {
            uint32_t adr = as_b + (uint32_t)(((m0 + mt * 16 + lr8 * 8 + l7) * 260
                                              + ks * 8 + lhi * 4) * 4);
            ldm_x4(aF[mt], adr);
        }
        uint32_t bF[4];
        uint32_t adr = buf_b + (uint32_t)(((j0 + lhi * 8 + l7) * 132 + (ks - 16) * 8 + lr8 * 4) * 4);
        ldm_x4(bF, adr);
#pragma unroll
        for (int mt = 0; mt < 2; mt++) {
            mma8(acc2[mt][0], aF[mt], bF);
            mma8(acc2[mt][1], aF[mt], bF + 2);
        }
    }
    __syncthreads();   // all H2 reads done before es overwrites As region

    // ---- epilogue2: es (tf32, [64][36] at As base) + act -------------------
    {
        const float fcab = fca_b[0];
#pragma unroll
        for (int mt = 0; mt < 2; mt++) {
            int r0 = m0 + mt * 16 + gr;
#pragma unroll
            for (int ntp = 0; ntp < 2; ntp++) {
                int col = j0 + ntp * 8 + 2 * tg;
                float* d = acc2[mt][ntp];
                if (col < 32) {
                    float b0 = fcebS[col], b1 = fcebS[col + 1];
                    AsU[r0 * 36 + col]           = f2tf(d[0] + b0);
                    AsU[r0 * 36 + col + 1]       = f2tf(d[1] + b1);
                    AsU[(r0 + 8) * 36 + col]     = f2tf(d[2] + b0);
                    AsU[(r0 + 8) * 36 + col + 1] = f2tf(d[3] + b1);
                } else if (col == 32) {
                    actS[r0]     = sigmoidf_(d[0] + fcab);
                    actS[r0 + 8] = sigmoidf_(d[2] + fcab);
                }
            }
        }
    }
    // load vs [256][36] into BUF via cp.async (We2T dead)
#pragma unroll
    for (int q = 0; q < 8; q++) {
        int s = t + 256 * q;
        int v = s >> 3, seg = s & 7;
        uint32_t dst = buf_b + (uint32_t)((v * 36 + seg * 4) * 4);
        CP_ASYNC16(dst, &g_vsu[v * 32 + seg * 4]);
    }
    CP_COMMIT();
    CP_WAIT0();
    __syncthreads();

    // ---- relation mma: M=64 n, N=256 v, K=32 -------------------------------
    const int v0 = wn * 64;
    float accr[2][8][4] = {};
#pragma unroll
    for (int ks = 0; ks < 4; ks++) {
        uint32_t aF[2][4];
#pragma unroll
        for (int mt = 0; mt < 2; mt++) {
            uint32_t adr = as_b + (uint32_t)(((m0 + mt * 16 + lr8 * 8 + l7) * 36
                                              + ks * 8 + lhi * 4) * 4);
            ldm_x4(aF[mt], adr);
        }
#pragma unroll
        for (int ntp = 0; ntp < 4; ntp++) {
            uint32_t bF[4];
            uint32_t adr = buf_b + (uint32_t)(((v0 + (ntp * 2 + lhi) * 8 + l7) * 36
                                               + ks * 8 + lr8 * 4) * 4);
            ldm_x4(bF, adr);
#pragma unroll
            for (int mt = 0; mt < 2; mt++) {
                mma8(accr[mt][2 * ntp],     aF[mt], bF);
                mma8(accr[mt][2 * ntp + 1], aF[mt], bF + 2);
            }
        }
    }

    // ---- softmax (registers + small smem combines) -------------------------
#pragma unroll
    for (int mt = 0; mt < 2; mt++) {
        float mxa = -1e30f, mxb = -1e30f;
#pragma unroll
        for (int nt = 0; nt < 8; nt++) {
            float* d = accr[mt][nt];
            mxa = fmaxf(mxa, fmaxf(d[0], d[1]));
            mxb = fmaxf(mxb, fmaxf(d[2], d[3]));
        }
        mxa = fmaxf(mxa, __shfl_xor_sync(0xffffffffu, mxa, 1));
        mxa = fmaxf(mxa, __shfl_xor_sync(0xffffffffu, mxa, 2));
        mxb = fmaxf(mxb, __shfl_xor_sync(0xffffffffu, mxb, 1));
        mxb = fmaxf(mxb, __shfl_xor_sync(0xffffffffu, mxb, 2));
        if (tg == 0) {
            redm[(m0 + mt * 16 + gr) * 4 + wn] = mxa;
            redm[(m0 + mt * 16 + 8 + gr) * 4 + wn] = mxb;
        }
    }
    __syncthreads();   // also: all relation reads of vs/es complete

    // issue VC chunks 0,1 ([128 c][32 v] each, stride 36) into BUF
    const uint32_t* Avcu = g_vcu + (size_t)b * CSZ * V_PIX;
#pragma unroll
    for (int c = 0; c < 2; c++) {
#pragma unroll
        for (int q = 0; q < 4; q++) {
            int s = t + 256 * q;
            int row = s >> 3, k4 = s & 7;
            uint32_t dst = buf_b + (uint32_t)((c * 4608 + row * 36 + k4 * 4) * 4);
            CP_ASYNC16(dst, Avcu + row * 256 + c * 32 + k4 * 4);
        }
        CP_COMMIT();
    }

#pragma unroll
    for (int mt = 0; mt < 2; mt++) {
        int na = m0 + mt * 16 + gr, nb = na + 8;
        float ma = fmaxf(fmaxf(redm[na * 4 + 0], redm[na * 4 + 1]),
                         fmaxf(redm[na * 4 + 2], redm[na * 4 + 3]));
        float mb = fmaxf(fmaxf(redm[nb * 4 + 0], redm[nb * 4 + 1]),
                         fmaxf(redm[nb * 4 + 2], redm[nb * 4 + 3]));
        float sa = 0.f, sb = 0.f;
#pragma unroll
        for (int nt = 0; nt < 8; nt++) {
            float* d = accr[mt][nt];
            d[0] = __expf(d[0] - ma); d[1] = __expf(d[1] - ma);
            d[2] = __expf(d[2] - mb); d[3] = __expf(d[3] - mb);
            sa += d[0] + d[1];
            sb += d[2] + d[3];
        }
        sa += __shfl_xor_sync(0xffffffffu, sa, 1);
        sa += __shfl_xor_sync(0xffffffffu, sa, 2);
        sb += __shfl_xor_sync(0xffffffffu, sb, 1);
        sb += __shfl_xor_sync(0xffffffffu, sb, 2);
        if (tg == 0) { reds[na * 4 + wn] = sa; reds[nb * 4 + wn] = sb; }
    }
    __syncthreads();

    // scale + write route [64 n][260 v] into As region (es dead)
#pragma unroll
    for (int mt = 0; mt < 2; mt++) {
        int na = m0 + mt * 16 + gr, nb = na + 8;
        float sA = reds[na * 4 + 0] + reds[na * 4 + 1] + reds[na * 4 + 2] + reds[na * 4 + 3];
        float sB = reds[nb * 4 + 0] + reds[nb * 4 + 1] + reds[nb * 4 + 2] + reds[nb * 4 + 3];
        float scA = actS[na] / sA;
        float scB = actS[nb] / sB;
#pragma unroll
        for (int nt = 0; nt < 8; nt++) {
            int v = v0 + nt * 8 + 2 * tg;
            float* d = accr[mt][nt];
            uint2 ua, ub;
            ua.x = f2tf(d[0] * scA); ua.y = f2tf(d[1] * scA);
            ub.x = f2tf(d[2] * scB); ub.y = f2tf(d[3] * scB);
            *(uint2*)&AsU[na * 260 + v] = ua;
            *(uint2*)&AsU[nb * 260 + v] = ub;
        }
    }
    __syncthreads();

    // ---- out GEMM: out[c][n] = VC @ route, M=128 c, N=64 n, K=256 ----------
    const int wm2 = wid >> 1, wn2 = wid & 1;
    const int c0 = wm2 * 32, n0o = wn2 * 32;
    float acco[2][4][4] = {};
    for (int c = 0; c < 8; c++) {
        if (c < 7) { CP_WAIT1(); } else { CP_WAIT0(); }
        __syncthreads();
        const uint32_t vcb = buf_b + (uint32_t)((c & 1) * 4608 * 4);
#pragma unroll
        for (int ks = 0; ks < 4; ks++) {
            uint32_t aF[2][4];
#pragma unroll
            for (int mt = 0; mt < 2; mt++) {
                uint32_t adr = vcb + (uint32_t)(((c0 + mt * 16 + lr8 * 8 + l7) * 36
                                                 + ks * 8 + lhi * 4) * 4);
                ldm_x4(aF[mt], adr);
            }
#pragma unroll
            for (int ntp = 0; ntp < 2; ntp++) {
                uint32_t bF[4];
                uint32_t adr = as_b + (uint32_t)(((n0o + (ntp * 2 + lhi) * 8 + l7) * 260
                                                  + c * 32 + ks * 8 + lr8 * 4) * 4);
                ldm_x4(bF, adr);
#pragma unroll
                for (int mt = 0; mt < 2; mt++) {
                    mma8(acco[mt][2 * ntp],     aF[mt], bF);
                    mma8(acco[mt][2 * ntp + 1], aF[mt], bF + 2);
                }
            }
        }
        if (c < 6) {
            __syncthreads();
            int cn = c + 2;
#pragma unroll
            for (int q = 0; q < 4; q++) {
                int s = t + 256 * q;
                int row = s >> 3, k4 = s & 7;
                uint32_t dst = buf_b + (uint32_t)(((cn & 1) * 4608 + row * 36 + k4 * 4) * 4);
                CP_ASYNC16(dst, Avcu + row * 256 + cn * 32 + k4 * 4);
            }
            CP_COMMIT();
        }
    }

    // ---- store out ----
#pragma unroll
    for (int mt = 0; mt < 2; mt++) {
#pragma unroll
        for (int nt = 0; nt < 4; nt++) {
            int r0 = c0 + mt * 16 + gr;
            int ng = n0g + n0o + nt * 8 + 2 * tg;
            float* d = acco[mt][nt];
            if (ng < N_WRD) {
                float2 s0; s0.x = d[0]; s0.y = d[1];
                float2 s1; s1.x = d[2]; s1.y = d[3];
                *(float2*)&out[((size_t)b * CSZ + r0) * N_WRD + ng]     = s0;
                *(float2*)&out[((size_t)b * CSZ + r0 + 8) * N_WRD + ng] = s1;
            }
        }
    }
}

// ---------------- launch --------------------------------------------------
extern "C" void kernel_launch(void* const* d_in, const int* in_sizes, int n_in,
                              void* d_out, int out_size) {
    const float* view_cell = (const float*)d_in[0];
    const float* v         = (const float*)d_in[1];
    const float* w2c_w1    = (const float*)d_in[2];
    const float* w2c_b1    = (const float*)d_in[3];
    const float* w2c_w2    = (const float*)d_in[4];
    const float* w2c_b2    = (const float*)d_in[5];
    const float* fc1_w     = (const float*)d_in[6];
    const float* fc1_b     = (const float*)d_in[7];
    const float* fc2_w     = (const float*)d_in[8];
    const float* fc2_b     = (const float*)d_in[9];
    const float* fca_w     = (const float*)d_in[10];
    const float* fca_b     = (const float*)d_in[11];
    const float* fce_w     = (const float*)d_in[12];
    const float* fce_b     = (const float*)d_in[13];
    const float* vse_w1    = (const float*)d_in[14];
    const float* vse_b1    = (const float*)d_in[15];
    const float* vse_w2    = (const float*)d_in[16];
    const float* vse_b2    = (const float*)d_in[17];
    float* out = (float*)d_out;

    static bool attr_set = false;
    if (!attr_set) {
        cudaFuncSetAttribute(k_AB, cudaFuncAttributeMaxDynamicSharedMemorySize, KF_TOT * 4);
        attr_set = true;
    }

    k_setup<<<352 + 2048, 256>>>(fc2_w, fce_w, fca_w, view_cell, v, w2c_w1, w2c_b1,
                                 vse_w1, vse_b1, vse_w2, vse_b2);
    k_wcode<<<(6000 + 63) / 64, 256>>>(w2c_w2, w2c_b2);
    dim3 gridF((N_WRD + 63) / 64, B_SZ);
    k_AB<<<gridF, 256, KF_TOT * 4>>>(fc1_w, fc1_b, fc2_b, fca_b, fce_b, out);
}

// round 9
// speedup vs baseline: 1.0823x; 1.0072x over previous
#include <cuda_runtime.h>
#include <cstdint>

#define N_WRD  2000
#define B_SZ   64
#define CSZ    128
#define V_PIX  256
#define EMB    32

// ---------------- scratch (device globals; no allocations allowed) ----------
__device__ float    g_wcode[B_SZ * 6000 + 192];         // padded for tile overrun
__device__ uint32_t g_vsu[V_PIX * EMB];                 // vs as tf32 bits
__device__ uint32_t g_w2tu[256 * 256];                  // fc2_w^T as tf32, [n][k]
__device__ uint32_t g_we2tu[64 * 256];                  // [fce|fca|0]^T tf32, [j][k]
__device__ uint32_t g_vcu[(size_t)B_SZ * CSZ * V_PIX];  // view_cell as tf32

// ============================ helpers =======================================
__device__ __forceinline__ uint32_t f2tf(float f) {
    uint32_t u; asm("cvt.rna.tf32.f32 %0, %1;" : "=r"(u) : "f"(f)); return u;
}
__device__ __forceinline__ void mma8(float* d, const uint32_t* a, const uint32_t* b) {
    asm volatile("mma.sync.aligned.m16n8k8.row.col.f32.tf32.tf32.f32 "
        "{%0,%1,%2,%3}, {%4,%5,%6,%7}, {%8,%9}, {%0,%1,%2,%3};"
        : "+f"(d[0]), "+f"(d[1]), "+f"(d[2]), "+f"(d[3])
        : "r"(a[0]), "r"(a[1]), "r"(a[2]), "r"(a[3]), "r"(b[0]), "r"(b[1]));
}
__device__ __forceinline__ void ldm_x4(uint32_t* r, uint32_t addr) {
    asm volatile("ldmatrix.sync.aligned.m8n8.x4.shared.b16 {%0,%1,%2,%3}, [%4];"
        : "=r"(r[0]), "=r"(r[1]), "=r"(r[2]), "=r"(r[3]) : "r"(addr));
}
__device__ __forceinline__ uint32_t smem_u32(const void* p) {
    uint32_t a;
    asm("{ .reg .u64 t; cvta.to.shared.u64 t, %1; cvt.u32.u64 %0, t; }"
        : "=r"(a) : "l"(p));
    return a;
}
#define CP_ASYNC16(dst, src) \
    asm volatile("cp.async.ca.shared.global [%0], [%1], 16;" :: "r"(dst), "l"(src))
#define CP_COMMIT() asm volatile("cp.async.commit_group;")
#define CP_WAIT0()  asm volatile("cp.async.wait_group 0;")
__device__ __forceinline__ float sigmoidf_(float x) {
    return 1.f / (1.f + __expf(-x));
}

// ====== setup kernel: weights + vs + VC convert + wcode (self-contained) ====
__global__ __launch_bounds__(256) void k_setup(
    const float* __restrict__ fc2_w, const float* __restrict__ fce_w,
    const float* __restrict__ fca_w, const float* __restrict__ vc_g,
    const float* __restrict__ v, const float* __restrict__ w2c_w1,
    const float* __restrict__ w2c_b1,
    const float* __restrict__ w2c_w2, const float* __restrict__ w2c_b2,
    const float* __restrict__ vse_w1, const float* __restrict__ vse_b1,
    const float* __restrict__ vse_w2, const float* __restrict__ vse_b2) {
    const int bid = blockIdx.x;
    const int t = threadIdx.x;
    if (bid < 256) {
        int k = bid;
        g_w2tu[t * 256 + k] = f2tf(fc2_w[k * 256 + t]);
        if (bid < 64) {
            int j = bid;
            float val = (j < 32) ? fce_w[t * 32 + j] : ((j == 32) ? fca_w[t] : 0.f);
            g_we2tu[j * 256 + t] = f2tf(val);
        }
    } else if (bid < 288) {
        int vl = t >> 5, e = t & 31;
        int vv = (bid - 256) * 8 + vl;
        float x = -1.f + (2.f / 15.f) * (float)(vv >> 4);
        float y = -1.f + (2.f / 15.f) * (float)(vv & 15);
        float acc = vse_b2[e];
#pragma unroll 4
        for (int j = 0; j < 128; j++) {
            float h = fmaxf(fmaf(x, vse_w1[j], fmaf(y, vse_w1[128 + j], vse_b1[j])), 0.f);
            acc = fmaf(h, vse_w2[j * EMB + e], acc);
        }
        g_vsu[vv * EMB + e] = f2tf(acc);
    } else if (bid < 2336) {
        size_t base = (size_t)(bid - 288) * 1024 + t * 4;
        float4 f = *(const float4*)&vc_g[base];
        uint4 u;
        u.x = f2tf(f.x); u.y = f2tf(f.y); u.z = f2tf(f.z); u.w = f2tf(f.w);
        *(uint4*)&g_vcu[base] = u;
    } else {
        // ---- wcode tile: 64 cols of 6000, recompute h0 on the fly ----
        __shared__ float As[64 * 33];
        __shared__ float Bs[32 * 68];
        __shared__ float vS[448];
        int tx = t & 15, ty = t >> 4;
        int n0 = (bid - 2336) * 64;
        for (int i = t; i < 448; i += 256) vS[i] = v[i];
        __syncthreads();
        float acc[4][4] = {};
        for (int k0 = 0; k0 < 512; k0 += 32) {
            for (int i = t; i < 2048; i += 256) {
                int r = i >> 5, k = i & 31;
                int kk = k0 + k;
                float a = w2c_b1[kk];
#pragma unroll
                for (int q = 0; q < 7; q++)
                    a = fmaf(vS[r * 7 + q], w2c_w1[q * 512 + kk], a);
                As[r * 33 + k] = fmaxf(a, 0.f);
            }
            for (int i = t; i < 2048; i += 256) {
                int k = i >> 6, n = i & 63;
                int nn = n0 + n;
                Bs[k * 68 + n] = (nn < 6000) ? w2c_w2[(k0 + k) * 6000 + nn] : 0.f;
            }
            __syncthreads();
#pragma unroll
            for (int k = 0; k < 32; k++) {
                float a[4], bb[4];
#pragma unroll
                for (int i = 0; i < 4; i++) a[i] = As[(4 * ty + i) * 33 + k];
#pragma unroll
                for (int j = 0; j < 4; j++) bb[j] = Bs[k * 68 + 4 * tx + j];
#pragma unroll
                for (int i = 0; i < 4; i++)
#pragma unroll
                    for (int j = 0; j < 4; j++) acc[i][j] = fmaf(a[i], bb[j], acc[i][j]);
            }
            __syncthreads();
        }
#pragma unroll
        for (int i = 0; i < 4; i++) {
            int r = 4 * ty + i;
#pragma unroll
            for (int j = 0; j < 4; j++) {
                int col = n0 + 4 * tx + j;
                if (col < 6000) g_wcode[r * 6000 + col] = acc[i][j] + w2c_b2[col];
            }
        }
    }
}

// ====== fused kernel: fc1 -> fc2 -> fce/fca -> relation -> softmax -> out ===
// smem floats:
#define KF_AS    0          // As [64][260]=16640: A -> H2 -> es([64][36]) -> route
#define KF_BUF   16640      // 10240: W2T dbuf 2x5120 / We2T dbuf 2x4352 / vs 9216 / VC dbuf 2x4608
#define KF_ACT   26880      // 64
#define KF_RM    26944      // 256
#define KF_RS    27200      // 256
#define KF_FC2B  27456      // 256
#define KF_FCEB  27712      // 32
#define KF_WC    27744      // 192
#define KF_TOT   27936      // -> 111744 bytes

__global__ __launch_bounds__(256, 2) void k_AB(
    const float* __restrict__ fc1_w, const float* __restrict__ fc1_b,
    const float* __restrict__ fc2_b,
    const float* __restrict__ fca_b, const float* __restrict__ fce_b,
    float* __restrict__ out) {
    extern __shared__ float sm[];
    uint32_t* AsU  = (uint32_t*)sm;
    float*    actS = sm + KF_ACT;
    float*    redm = sm + KF_RM;
    float*    reds = sm + KF_RS;
    float*    fc2bS= sm + KF_FC2B;
    float*    fcebS= sm + KF_FCEB;
    float*    wcS  = sm + KF_WC;

    const uint32_t as_b  = smem_u32(sm);
    const uint32_t buf_b = smem_u32(sm + KF_BUF);

    const int t = threadIdx.x;
    const int wid = t >> 5, lane = t & 31;
    const int gr = lane >> 2, tg = lane & 3;
    const int lr8 = (lane >> 3) & 1, l7 = lane & 7, lhi = lane >> 4;
    const int n0g = blockIdx.x * 64;       // word tile within batch
    const int b   = blockIdx.y;
    const int row0g = b * N_WRD + n0g;     // global word row

    // ---- consts + wcode rows ----
    fc2bS[t] = fc2_b[t];
    if (t < 32) fcebS[t] = fce_b[t];
    if (t < 192) wcS[t] = g_wcode[row0g * 3 + t];

    // preload W2T chunk 0 ([256 n][16 k], stride 20)
#pragma unroll
    for (int q = 0; q < 4; q++) {
        int s = t + 256 * q;
        int n = s >> 2, kq = s & 3;
        uint32_t dst = buf_b + (uint32_t)((n * 20 + kq * 4) * 4);
        CP_ASYNC16(dst, &g_w2tu[n * 256 + kq * 4]);
    }
    CP_COMMIT();
    __syncthreads();

    // ---- fc1 -> As tf32 ----
    {
        int r = t >> 2, kb = (t & 3) * 64;
        float w0 = wcS[r * 3 + 0], w1 = wcS[r * 3 + 1], w2 = wcS[r * 3 + 2];
        for (int j = 0; j < 64; j += 4) {
            uint4 u;
            int k = kb + j;
            u.x = f2tf(fmaxf(fmaf(w0, fc1_w[k+0], fmaf(w1, fc1_w[256+k+0], fmaf(w2, fc1_w[512+k+0], fc1_b[k+0]))), 0.f));
            u.y = f2tf(fmaxf(fmaf(w0, fc1_w[k+1], fmaf(w1, fc1_w[256+k+1], fmaf(w2, fc1_w[512+k+1], fc1_b[k+1]))), 0.f));
            u.z = f2tf(fmaxf(fmaf(w0, fc1_w[k+2], fmaf(w1, fc1_w[256+k+2], fmaf(w2, fc1_w[512+k+2], fc1_b[k+2]))), 0.f));
            u.w = f2tf(fmaxf(fmaf(w0, fc1_w[k+3], fmaf(w1, fc1_w[256+k+3], fmaf(w2, fc1_w[512+k+3], fc1_b[k+3]))), 0.f));
            *(uint4*)&AsU[r * 260 + k] = u;
        }
    }

    // ---- MMA1: H2raw = A @ W2 (64x256, K=256). warps: 2m x 4n.
    // single-sync pipeline: wait; sync; issue next; compute.
    const int wm = wid & 1, wn = wid >> 1;
    const int m0 = wm * 32, n0 = wn * 64;
    {
        float acc1[2][8][4] = {};
        for (int kc = 0; kc < 16; kc++) {
            CP_WAIT0();
            __syncthreads();
            if (kc < 15) {
                int cn = kc + 1;
#pragma unroll
                for (int q = 0; q < 4; q++) {
                    int s = t + 256 * q;
                    int n = s >> 2, kq = s & 3;
                    uint32_t dst = buf_b + (uint32_t)(((cn & 1) * 5120 + n * 20 + kq * 4) * 4);
                    CP_ASYNC16(dst, &g_w2tu[n * 256 + cn * 16 + kq * 4]);
                }
                CP_COMMIT();
            }
            const uint32_t buf = buf_b + (uint32_t)((kc & 1) * 5120 * 4);
#pragma unroll
            for (int ks2 = 0; ks2 < 2; ks2++) {
                uint32_t aF[2][4];
#pragma unroll
                for (int mt = 0; mt < 2; mt++) {
                    uint32_t adr = as_b + (uint32_t)(((m0 + mt * 16 + lr8 * 8 + l7) * 260
                                                      + kc * 16 + ks2 * 8 + lhi * 4) * 4);
                    ldm_x4(aF[mt], adr);
                }
#pragma unroll
                for (int ntp = 0; ntp < 4; ntp++) {
                    uint32_t bF[4];
                    uint32_t adr = buf + (uint32_t)(((n0 + (ntp * 2 + lhi) * 8 + l7) * 20
                                                     + ks2 * 8 + lr8 * 4) * 4);
                    ldm_x4(bF, adr);
#pragma unroll
                    for (int mt = 0; mt < 2; mt++) {
                        mma8(acc1[mt][2 * ntp],     aF[mt], bF);
                        mma8(acc1[mt][2 * ntp + 1], aF[mt], bF + 2);
                    }
                }
            }
        }
        __syncthreads();   // all MMA1 reads of As and BUF complete

        // preload We2T chunk 0 ([64 j][64 k], stride 68) during epilogue1
#pragma unroll
        for (int q = 0; q < 4; q++) {
            int s = t + 256 * q;
            int j = s >> 4, kq = s & 15;
            uint32_t dst = buf_b + (uint32_t)((j * 68 + kq * 4) * 4);
            CP_ASYNC16(dst, &g_we2tu[j * 256 + kq * 4]);
        }
        CP_COMMIT();

        // epilogue1: H2 = relu(acc + bias) -> As tf32
#pragma unroll
        for (int mt = 0; mt < 2; mt++) {
#pragma unroll
            for (int nt = 0; nt < 8; nt++) {
                int col = n0 + nt * 8 + 2 * tg;
                int r0 = m0 + mt * 16 + gr;
                float b0 = fc2bS[col], b1 = fc2bS[col + 1];
                float* d = acc1[mt][nt];
                uint2 u0, u1;
                u0.x = f2tf(fmaxf(d[0] + b0, 0.f));
                u0.y = f2tf(fmaxf(d[1] + b1, 0.f));
                u1.x = f2tf(fmaxf(d[2] + b0, 0.f));
                u1.y = f2tf(fmaxf(d[3] + b1, 0.f));
                *(uint2*)&AsU[r0 * 260 + col]       = u0;
                *(uint2*)&AsU[(r0 + 8) * 260 + col] = u1;
            }
        }
    }

    // ---- MMA2: D2 = H2 @ We2 (64x64, K=256 in 4 chunks of 64, dbuf) --------
    const int j0 = wn * 16;
    float acc2[2][2][4] = {};
    for (int q = 0; q < 4; q++) {
        CP_WAIT0();
        __syncthreads();
        if (q < 3) {
            int qn = q + 1;
#pragma unroll
            for (int qq = 0; qq < 4; qq++) {
                int s = t + 256 * qq;
                int j = s >> 4, kq = s & 15;
                uint32_t dst = buf_b + (uint32_t)(((qn & 1) * 4352 + j * 68 + kq * 4) * 4);
                CP_ASYNC16(dst, &g_we2tu[j * 256 + qn * 64 + kq * 4]);
            }
            CP_COMMIT();
        }
        const uint32_t buf = buf_b + (uint32_t)((q & 1) * 4352 * 4);
#pragma unroll
        for (int ks = 0; ks < 8; ks++) {
            uint32_t aF[2][4];
#pragma unroll
            for (int mt = 0; mt < 2; mt++) {
                uint32_t adr = as_b + (uint32_t)(((m0 + mt * 16 + lr8 * 8 + l7) * 260
                                                  + q * 64 + ks * 8 + lhi * 4) * 4);
                ldm_x4(aF[mt], adr);
            }
            uint32_t bF[4];
            uint32_t adr = buf + (uint32_t)(((j0 + lhi * 8 + l7) * 68 + ks * 8 + lr8 * 4) * 4);
            ldm_x4(bF, adr);
#pragma unroll
            for (int mt = 0; mt < 2; mt++) {
                mma8(acc2[mt][0], aF[mt], bF);
                mma8(acc2[mt][1], aF[mt], bF + 2);
            }
        }
    }
    __syncthreads();   // all H2/We2T reads done

    // issue vs load ([256 v][36], overlaps epilogue2)
#pragma unroll
    for (int q = 0; q < 9; q++) {
        int s = t + 256 * q;
        int v = s >> 3, seg = s & 7;
        if (v < 256) {
            uint32_t dst = buf_b + (uint32_t)((v * 36 + seg * 4) * 4);
            CP_ASYNC16(dst, &g_vsu[v * 32 + seg * 4]);
        }
    }
    CP_COMMIT();

    // ---- epilogue2: es (tf32, [64][36] at As base) + act -------------------
    {
        const float fcab = fca_b[0];
#pragma unroll
        for (int mt = 0; mt < 2; mt++) {
            int r0 = m0 + mt * 16 + gr;
#pragma unroll
            for (int ntp = 0; ntp < 2; ntp++) {
                int col = j0 + ntp * 8 + 2 * tg;
                float* d = acc2[mt][ntp];
                if (col < 32) {
                    float b0 = fcebS[col], b1 = fcebS[col + 1];
                    AsU[r0 * 36 + col]           = f2tf(d[0] + b0);
                    AsU[r0 * 36 + col + 1]       = f2tf(d[1] + b1);
                    AsU[(r0 + 8) * 36 + col]     = f2tf(d[2] + b0);
                    AsU[(r0 + 8) * 36 + col + 1] = f2tf(d[3] + b1);
                } else if (col == 32) {
                    actS[r0]     = sigmoidf_(d[0] + fcab);
                    actS[r0 + 8] = sigmoidf_(d[2] + fcab);
                }
            }
        }
    }
    CP_WAIT0();
    __syncthreads();

    // ---- relation mma: M=64 n, N=256 v, K=32 -------------------------------
    const int v0 = wn * 64;
    float accr[2][8][4] = {};
#pragma unroll
    for (int ks = 0; ks < 4; ks++) {
        uint32_t aF[2][4];
#pragma unroll
        for (int mt = 0; mt < 2; mt++) {
            uint32_t adr = as_b + (uint32_t)(((m0 + mt * 16 + lr8 * 8 + l7) * 36
                                              + ks * 8 + lhi * 4) * 4);
            ldm_x4(aF[mt], adr);
        }
#pragma unroll
        for (int ntp = 0; ntp < 4; ntp++) {
            uint32_t bF[4];
            uint32_t adr = buf_b + (uint32_t)(((v0 + (ntp * 2 + lhi) * 8 + l7) * 36
                                               + ks * 8 + lr8 * 4) * 4);
            ldm_x4(bF, adr);
#pragma unroll
            for (int mt = 0; mt < 2; mt++) {
                mma8(accr[mt][2 * ntp],     aF[mt], bF);
                mma8(accr[mt][2 * ntp + 1], aF[mt], bF + 2);
            }
        }
    }

    // ---- softmax (registers + small smem combines) -------------------------
#pragma unroll
    for (int mt = 0; mt < 2; mt++) {
        float mxa = -1e30f, mxb = -1e30f;
#pragma unroll
        for (int nt = 0; nt < 8; nt++) {
            float* d = accr[mt][nt];
            mxa = fmaxf(mxa, fmaxf(d[0], d[1]));
            mxb = fmaxf(mxb, fmaxf(d[2], d[3]));
        }
        mxa = fmaxf(mxa, __shfl_xor_sync(0xffffffffu, mxa, 1));
        mxa = fmaxf(mxa, __shfl_xor_sync(0xffffffffu, mxa, 2));
        mxb = fmaxf(mxb, __shfl_xor_sync(0xffffffffu, mxb, 1));
        mxb = fmaxf(mxb, __shfl_xor_sync(0xffffffffu, mxb, 2));
        if (tg == 0) {
            redm[(m0 + mt * 16 + gr) * 4 + wn] = mxa;
            redm[(m0 + mt * 16 + 8 + gr) * 4 + wn] = mxb;
        }
    }
    __syncthreads();   // relation reads of vs/es complete; redm visible

    // issue VC chunk 0 ([128 c][32 v], stride 36)
    const uint32_t* Avcu = g_vcu + (size_t)b * CSZ * V_PIX;
#pragma unroll
    for (int q = 0; q < 4; q++) {
        int s = t + 256 * q;
        int row = s >> 3, k4 = s & 7;
        uint32_t dst = buf_b + (uint32_t)((row * 36 + k4 * 4) * 4);
        CP_ASYNC16(dst, Avcu + row * 256 + k4 * 4);
    }
    CP_COMMIT();

#pragma unroll
    for (int mt = 0; mt < 2; mt++) {
        int na = m0 + mt * 16 + gr, nb = na + 8;
        float ma = fmaxf(fmaxf(redm[na * 4 + 0], redm[na * 4 + 1]),
                         fmaxf(redm[na * 4 + 2], redm[na * 4 + 3]));
        float mb = fmaxf(fmaxf(redm[nb * 4 + 0], redm[nb * 4 + 1]),
                         fmaxf(redm[nb * 4 + 2], redm[nb * 4 + 3]));
        float sa = 0.f, sb = 0.f;
#pragma unroll
        for (int nt = 0; nt < 8; nt++) {
            float* d = accr[mt][nt];
            d[0] = __expf(d[0] - ma); d[1] = __expf(d[1] - ma);
            d[2] = __expf(d[2] - mb); d[3] = __expf(d[3] - mb);
            sa += d[0] + d[1];
            sb += d[2] + d[3];
        }
        sa += __shfl_xor_sync(0xffffffffu, sa, 1);
        sa += __shfl_xor_sync(0xffffffffu, sa, 2);
        sb += __shfl_xor_sync(0xffffffffu, sb, 1);
        sb += __shfl_xor_sync(0xffffffffu, sb, 2);
        if (tg == 0) { reds[na * 4 + wn] = sa; reds[nb * 4 + wn] = sb; }
    }
    __syncthreads();

    // scale + write route [64 n][260 v] into As region (es dead)
#pragma unroll
    for (int mt = 0; mt < 2; mt++) {
        int na = m0 + mt * 16 + gr, nb = na + 8;
        float sA = reds[na * 4 + 0] + reds[na * 4 + 1] + reds[na * 4 + 2] + reds[na * 4 + 3];
        float sB = reds[nb * 4 + 0] + reds[nb * 4 + 1] + reds[nb * 4 + 2] + reds[nb * 4 + 3];
        float scA = actS[na] / sA;
        float scB = actS[nb] / sB;
#pragma unroll
        for (int nt = 0; nt < 8; nt++) {
            int v = v0 + nt * 8 + 2 * tg;
            float* d = accr[mt][nt];
            uint2 ua, ub;
            ua.x = f2tf(d[0] * scA); ua.y = f2tf(d[1] * scA);
            ub.x = f2tf(d[2] * scB); ub.y = f2tf(d[3] * scB);
            *(uint2*)&AsU[na * 260 + v] = ua;
            *(uint2*)&AsU[nb * 260 + v] = ub;
        }
    }

    // ---- out GEMM: out[c][n] = VC @ route, M=128 c, N=64 n, K=256 ----------
    // single-sync pipeline over 8 VC chunks
    const int wm2 = wid >> 1, wn2 = wid & 1;
    const int c0 = wm2 * 32, n0o = wn2 * 32;
    float acco[2][4][4] = {};
    for (int c = 0; c < 8; c++) {
        CP_WAIT0();
        __syncthreads();   // (c==0: also makes route writes visible)
        if (c < 7) {
            int cn = c + 1;
#pragma unroll
            for (int q = 0; q < 4; q++) {
                int s = t + 256 * q;
                int row = s >> 3, k4 = s & 7;
                uint32_t dst = buf_b + (uint32_t)(((cn & 1) * 4608 + row * 36 + k4 * 4) * 4);
                CP_ASYNC16(dst, Avcu + row * 256 + cn * 32 + k4 * 4);
            }
            CP_COMMIT();
        }
        const uint32_t vcb = buf_b + (uint32_t)((c & 1) * 4608 * 4);
#pragma unroll
        for (int ks = 0; ks < 4; ks++) {
            uint32_t aF[2][4];
#pragma unroll
            for (int mt = 0; mt < 2; mt++) {
                uint32_t adr = vcb + (uint32_t)(((c0 + mt * 16 + lr8 * 8 + l7) * 36
                                                 + ks * 8 + lhi * 4) * 4);
                ldm_x4(aF[mt], adr);
            }
#pragma unroll
            for (int ntp = 0; ntp < 2; ntp++) {
                uint32_t bF[4];
                uint32_t adr = as_b + (uint32_t)(((n0o + (ntp * 2 + lhi) * 8 + l7) * 260
                                                  + c * 32 + ks * 8 + lr8 * 4) * 4);
                ldm_x4(bF, adr);
#pragma unroll
                for (int mt = 0; mt < 2; mt++) {
                    mma8(acco[mt][2 * ntp],     aF[mt], bF);
                    mma8(acco[mt][2 * ntp + 1], aF[mt], bF + 2);
                }
            }
        }
    }

    // ---- store out ----
#pragma unroll
    for (int mt = 0; mt < 2; mt++) {
#pragma unroll
        for (int nt = 0; nt < 4; nt++) {
            int r0 = c0 + mt * 16 + gr;
            int ng = n0g + n0o + nt * 8 + 2 * tg;
            float* d = acco[mt][nt];
            if (ng < N_WRD) {
                float2 s0; s0.x = d[0]; s0.y = d[1];
                float2 s1; s1.x = d[2]; s1.y = d[3];
                *(float2*)&out[((size_t)b * CSZ + r0) * N_WRD + ng]     = s0;
                *(float2*)&out[((size_t)b * CSZ + r0 + 8) * N_WRD + ng] = s1;
            }
        }
    }
}

// ---------------- launch --------------------------------------------------
extern "C" void kernel_launch(void* const* d_in, const int* in_sizes, int n_in,
                              void* d_out, int out_size) {
    const float* view_cell = (const float*)d_in[0];
    const float* v         = (const float*)d_in[1];
    const float* w2c_w1    = (const float*)d_in[2];
    const float* w2c_b1    = (const float*)d_in[3];
    const float* w2c_w2    = (const float*)d_in[4];
    const float* w2c_b2    = (const float*)d_in[5];
    const float* fc1_w     = (const float*)d_in[6];
    const float* fc1_b     = (const float*)d_in[7];
    const float* fc2_w     = (const float*)d_in[8];
    const float* fc2_b     = (const float*)d_in[9];
    const float* fca_w     = (const float*)d_in[10];
    const float* fca_b     = (const float*)d_in[11];
    const float* fce_w     = (const float*)d_in[12];
    const float* fce_b     = (const float*)d_in[13];
    const float* vse_w1    = (const float*)d_in[14];
    const float* vse_b1    = (const float*)d_in[15];
    const float* vse_w2    = (const float*)d_in[16];
    const float* vse_b2    = (const float*)d_in[17];
    float* out = (float*)d_out;

    static bool attr_set = false;
    if (!attr_set) {
        cudaFuncSetAttribute(k_AB, cudaFuncAttributeMaxDynamicSharedMemorySize, KF_TOT * 4);
        attr_set = true;
    }

    k_setup<<<2430, 256>>>(fc2_w, fce_w, fca_w, view_cell, v, w2c_w1, w2c_b1,
                           w2c_w2, w2c_b2, vse_w1, vse_b1, vse_w2, vse_b2);
    dim3 gridF((N_WRD + 63) / 64, B_SZ);
    k_AB<<<gridF, 256, KF_TOT * 4>>>(fc1_w, fc1_b, fc2_b, fca_b, fce_b, out);
}

// round 10
// speedup vs baseline: 1.2914x; 1.1932x over previous
#include <cuda_runtime.h>
#include <cstdint>

#define N_WRD  2000
#define B_SZ   64
#define CSZ    128
#define V_PIX  256
#define EMB    32

// ---------------- scratch (device globals; no allocations allowed) ----------
__device__ float    g_wcode[B_SZ * 6000 + 192];          // padded for tile overrun
__device__ uint32_t g_w2f[32 * 32 * 64];                 // W2 B-frags [k8][n8][64]
__device__ uint32_t g_we2f[32 * 8 * 64];                 // We2 B-frags [k8][j8][64]
__device__ uint32_t g_vsf[4 * 32 * 64];                  // vs B-frags [e8][v8][64]
__device__ uint32_t g_vcf[(size_t)B_SZ * 32 * 8 * 128];  // VC A-frags [b][v8][c16][128]

// ============================ helpers =======================================
__device__ __forceinline__ uint32_t f2tf(float f) {
    uint32_t u; asm("cvt.rna.tf32.f32 %0, %1;" : "=r"(u) : "f"(f)); return u;
}
__device__ __forceinline__ void mma8(float* d, const uint32_t* a, const uint32_t* b) {
    asm volatile("mma.sync.aligned.m16n8k8.row.col.f32.tf32.tf32.f32 "
        "{%0,%1,%2,%3}, {%4,%5,%6,%7}, {%8,%9}, {%0,%1,%2,%3};"
        : "+f"(d[0]), "+f"(d[1]), "+f"(d[2]), "+f"(d[3])
        : "r"(a[0]), "r"(a[1]), "r"(a[2]), "r"(a[3]), "r"(b[0]), "r"(b[1]));
}
__device__ __forceinline__ void ldm_x4(uint32_t* r, uint32_t addr) {
    asm volatile("ldmatrix.sync.aligned.m8n8.x4.shared.b16 {%0,%1,%2,%3}, [%4];"
        : "=r"(r[0]), "=r"(r[1]), "=r"(r[2]), "=r"(r[3]) : "r"(addr));
}
__device__ __forceinline__ uint32_t smem_u32(const void* p) {
    uint32_t a;
    asm("{ .reg .u64 t; cvta.to.shared.u64 t, %1; cvt.u32.u64 %0, t; }"
        : "=r"(a) : "l"(p));
    return a;
}
__device__ __forceinline__ float sigmoidf_(float x) {
    return 1.f / (1.f + __expf(-x));
}

// ====== setup kernel: fragment packing + vs + VC pack + wcode ===============
// blocks: [0,256) w2f | [256,320) we2f | [320,352) vsf | [352,2400) vcf | [2400,2494) wcode
__global__ __launch_bounds__(256) void k_setup(
    const float* __restrict__ fc2_w, const float* __restrict__ fce_w,
    const float* __restrict__ fca_w, const float* __restrict__ vc_g,
    const float* __restrict__ v, const float* __restrict__ w2c_w1,
    const float* __restrict__ w2c_b1,
    const float* __restrict__ w2c_w2, const float* __restrict__ w2c_b2,
    const float* __restrict__ vse_w1, const float* __restrict__ vse_b1,
    const float* __restrict__ vse_w2, const float* __restrict__ vse_b2) {
    const int bid = blockIdx.x;
    const int t = threadIdx.x;
    if (bid < 256) {
        // W2 B-frags: b0 = fc2_w[k][n] with k = k8*8 + tg + half*4, n = n8*8 + gr
        int idx = bid * 256 + t;
        int k8 = idx >> 11, rem = idx & 2047;
        int n8 = rem >> 6, w = rem & 63;
        int l = w >> 1, half = w & 1;
        int k = k8 * 8 + (l & 3) + half * 4;
        int n = n8 * 8 + (l >> 2);
        g_w2f[idx] = f2tf(fc2_w[k * 256 + n]);
        if (bid < 64) {
            // We2 B-frags
            int idx2 = bid * 256 + t;
            int k8b = idx2 >> 9, rem2 = idx2 & 511;
            int j8 = rem2 >> 6, w2 = rem2 & 63;
            int l2 = w2 >> 1, h2 = w2 & 1;
            int kk = k8b * 8 + (l2 & 3) + h2 * 4;
            int j = j8 * 8 + (l2 >> 2);
            float val = (j < 32) ? fce_w[kk * 32 + j] : ((j == 32) ? fca_w[kk] : 0.f);
            g_we2f[idx2] = f2tf(val);
        }
    } else if (bid < 320) {
        // vs B-frags: b0 = vs[v][e], v = v8*8+gr, e = e8*8+tg+half*4
        int idx = (bid - 256) * 256 + t;          // [0, 16384) but only 8192 valid
        if (idx < 8192) {
            int e8 = idx >> 11, rem = idx & 2047;
            int v8 = rem >> 6, w = rem & 63;
            int l = w >> 1, half = w & 1;
            int vv = v8 * 8 + (l >> 2);
            int e  = e8 * 8 + (l & 3) + half * 4;
            float x = -1.f + (2.f / 15.f) * (float)(vv >> 4);
            float y = -1.f + (2.f / 15.f) * (float)(vv & 15);
            float acc = vse_b2[e];
#pragma unroll 4
            for (int j = 0; j < 128; j++) {
                float h = fmaxf(fmaf(x, vse_w1[j], fmaf(y, vse_w1[128 + j], vse_b1[j])), 0.f);
                acc = fmaf(h, vse_w2[j * EMB + e], acc);
            }
            g_vsf[idx] = f2tf(acc);
        }
    } else if (bid < 2400) {
        // VC A-frags: per block = (b, v8); a0=(c16*16+gr, v8*8+tg), a1=c+8, a2=v+4, a3=both
        int blk = bid - 352;
        int b = blk >> 5, v8 = blk & 31;
        for (int i = t; i < 1024; i += 256) {
            int c16 = i >> 7, w = i & 127;
            int l = w >> 2, q = w & 3;
            int c = c16 * 16 + (l >> 2) + (q & 1) * 8;
            int vv = v8 * 8 + (l & 3) + (q >> 1) * 4;
            g_vcf[((size_t)(b * 32 + v8) * 8 + c16) * 128 + w] =
                f2tf(vc_g[((size_t)b * CSZ + c) * V_PIX + vv]);
        }
    } else {
        // ---- wcode tile: 64 cols of 6000, recompute h0 on the fly ----
        __shared__ float As[64 * 33];
        __shared__ float Bs[32 * 68];
        __shared__ float vS[448];
        int tx = t & 15, ty = t >> 4;
        int n0 = (bid - 2400) * 64;
        for (int i = t; i < 448; i += 256) vS[i] = v[i];
        __syncthreads();
        float acc[4][4] = {};
        for (int k0 = 0; k0 < 512; k0 += 32) {
            for (int i = t; i < 2048; i += 256) {
                int r = i >> 5, k = i & 31;
                int kk = k0 + k;
                float a = w2c_b1[kk];
#pragma unroll
                for (int q = 0; q < 7; q++)
                    a = fmaf(vS[r * 7 + q], w2c_w1[q * 512 + kk], a);
                As[r * 33 + k] = fmaxf(a, 0.f);
            }
            for (int i = t; i < 2048; i += 256) {
                int k = i >> 6, n = i & 63;
                int nn = n0 + n;
                Bs[k * 68 + n] = (nn < 6000) ? w2c_w2[(k0 + k) * 6000 + nn] : 0.f;
            }
            __syncthreads();
#pragma unroll
            for (int k = 0; k < 32; k++) {
                float a[4], bb[4];
#pragma unroll
                for (int i = 0; i < 4; i++) a[i] = As[(4 * ty + i) * 33 + k];
#pragma unroll
                for (int j = 0; j < 4; j++) bb[j] = Bs[k * 68 + 4 * tx + j];
#pragma unroll
                for (int i = 0; i < 4; i++)
#pragma unroll
                    for (int j = 0; j < 4; j++) acc[i][j] = fmaf(a[i], bb[j], acc[i][j]);
            }
            __syncthreads();
        }
#pragma unroll
        for (int i = 0; i < 4; i++) {
            int r = 4 * ty + i;
#pragma unroll
            for (int j = 0; j < 4; j++) {
                int col = n0 + 4 * tx + j;
                if (col < 6000) g_wcode[r * 6000 + col] = acc[i][j] + w2c_b2[col];
            }
        }
    }
}

// ====== fused kernel: fc1 -> fc2 -> fce/fca -> relation -> softmax -> out ===
// smem floats: As [64][260] (A -> H2 -> es[64][36] -> route) + small
#define KF_AS    0
#define KF_ACT   16640      // 64
#define KF_RM    16704      // 256
#define KF_RS    16960      // 256
#define KF_FC2B  17216      // 256
#define KF_FCEB  17472      // 32
#define KF_WC    17504      // 192
#define KF_TOT   17696      // -> 70784 bytes

__global__ __launch_bounds__(256, 2) void k_AB(
    const float* __restrict__ fc1_w, const float* __restrict__ fc1_b,
    const float* __restrict__ fc2_b,
    const float* __restrict__ fca_b, const float* __restrict__ fce_b,
    float* __restrict__ out) {
    extern __shared__ float sm[];
    uint32_t* AsU  = (uint32_t*)sm;
    float*    actS = sm + KF_ACT;
    float*    redm = sm + KF_RM;
    float*    reds = sm + KF_RS;
    float*    fc2bS= sm + KF_FC2B;
    float*    fcebS= sm + KF_FCEB;
    float*    wcS  = sm + KF_WC;

    const uint32_t as_b = smem_u32(sm);

    const int t = threadIdx.x;
    const int wid = t >> 5, lane = t & 31;
    const int gr = lane >> 2, tg = lane & 3;
    const int lr8 = (lane >> 3) & 1, l7 = lane & 7, lhi = lane >> 4;
    const int n0g = blockIdx.x * 64;
    const int b   = blockIdx.y;
    const int row0g = b * N_WRD + n0g;

    // ---- consts + wcode rows ----
    fc2bS[t] = fc2_b[t];
    if (t < 32) fcebS[t] = fce_b[t];
    if (t < 192) wcS[t] = g_wcode[row0g * 3 + t];
    __syncthreads();

    // ---- fc1 -> As tf32 ----
    {
        int r = t >> 2, kb = (t & 3) * 64;
        float w0 = wcS[r * 3 + 0], w1 = wcS[r * 3 + 1], w2 = wcS[r * 3 + 2];
        for (int j = 0; j < 64; j += 4) {
            uint4 u;
            int k = kb + j;
            u.x = f2tf(fmaxf(fmaf(w0, fc1_w[k+0], fmaf(w1, fc1_w[256+k+0], fmaf(w2, fc1_w[512+k+0], fc1_b[k+0]))), 0.f));
            u.y = f2tf(fmaxf(fmaf(w0, fc1_w[k+1], fmaf(w1, fc1_w[256+k+1], fmaf(w2, fc1_w[512+k+1], fc1_b[k+1]))), 0.f));
            u.z = f2tf(fmaxf(fmaf(w0, fc1_w[k+2], fmaf(w1, fc1_w[256+k+2], fmaf(w2, fc1_w[512+k+2], fc1_b[k+2]))), 0.f));
            u.w = f2tf(fmaxf(fmaf(w0, fc1_w[k+3], fmaf(w1, fc1_w[256+k+3], fmaf(w2, fc1_w[512+k+3], fc1_b[k+3]))), 0.f));
            *(uint4*)&AsU[r * 260 + k] = u;
        }
    }
    __syncthreads();

    // ---- MMA1: H2raw = A @ W2 (64x256, K=256). warps 2m x 4n; B via LDG ----
    const int wm = wid & 1, wn = wid >> 1;
    const int m0 = wm * 32, n0 = wn * 64;
    {
        const uint32_t* w2p = g_w2f + (wn * 8) * 64 + lane * 2;
        uint2 curB[8], nxtB[8];
#pragma unroll
        for (int j = 0; j < 8; j++) curB[j] = *(const uint2*)(w2p + j * 64);
        float acc1[2][8][4] = {};
        for (int k8 = 0; k8 < 32; k8++) {
            if (k8 < 31) {
                const uint32_t* p = w2p + (k8 + 1) * 2048;
#pragma unroll
                for (int j = 0; j < 8; j++) nxtB[j] = *(const uint2*)(p + j * 64);
            }
            uint32_t aF[2][4];
#pragma unroll
            for (int mt = 0; mt < 2; mt++) {
                uint32_t adr = as_b + (uint32_t)(((m0 + mt * 16 + lr8 * 8 + l7) * 260
                                                  + k8 * 8 + lhi * 4) * 4);
                ldm_x4(aF[mt], adr);
            }
#pragma unroll
            for (int j = 0; j < 8; j++)
#pragma unroll
                for (int mt = 0; mt < 2; mt++)
                    mma8(acc1[mt][j], aF[mt], (const uint32_t*)&curB[j]);
#pragma unroll
            for (int j = 0; j < 8; j++) curB[j] = nxtB[j];
        }
        __syncthreads();   // all MMA1 reads of As done

        // epilogue1: H2 = relu(acc + bias) -> As tf32
#pragma unroll
        for (int mt = 0; mt < 2; mt++) {
#pragma unroll
            for (int nt = 0; nt < 8; nt++) {
                int col = n0 + nt * 8 + 2 * tg;
                int r0 = m0 + mt * 16 + gr;
                float b0 = fc2bS[col], b1 = fc2bS[col + 1];
                float* d = acc1[mt][nt];
                uint2 u0, u1;
                u0.x = f2tf(fmaxf(d[0] + b0, 0.f));
                u0.y = f2tf(fmaxf(d[1] + b1, 0.f));
                u1.x = f2tf(fmaxf(d[2] + b0, 0.f));
                u1.y = f2tf(fmaxf(d[3] + b1, 0.f));
                *(uint2*)&AsU[r0 * 260 + col]       = u0;
                *(uint2*)&AsU[(r0 + 8) * 260 + col] = u1;
            }
        }
    }
    __syncthreads();

    // ---- MMA2: D2 = H2 @ We2 (64x64, K=256); B via LDG ---------------------
    const int j0 = wn * 16;
    float acc2[2][2][4] = {};
    {
        const uint32_t* wep = g_we2f + (wn * 2) * 64 + lane * 2;
        uint2 curW[2], nxtW[2];
#pragma unroll
        for (int jj = 0; jj < 2; jj++) curW[jj] = *(const uint2*)(wep + jj * 64);
        for (int k8 = 0; k8 < 32; k8++) {
            if (k8 < 31) {
                const uint32_t* p = wep + (k8 + 1) * 512;
#pragma unroll
                for (int jj = 0; jj < 2; jj++) nxtW[jj] = *(const uint2*)(p + jj * 64);
            }
            uint32_t aF[2][4];
#pragma unroll
            for (int mt = 0; mt < 2; mt++) {
                uint32_t adr = as_b + (uint32_t)(((m0 + mt * 16 + lr8 * 8 + l7) * 260
                                                  + k8 * 8 + lhi * 4) * 4);
                ldm_x4(aF[mt], adr);
            }
#pragma unroll
            for (int jj = 0; jj < 2; jj++)
#pragma unroll
                for (int mt = 0; mt < 2; mt++)
                    mma8(acc2[mt][jj], aF[mt], (const uint32_t*)&curW[jj]);
#pragma unroll
            for (int jj = 0; jj < 2; jj++) curW[jj] = nxtW[jj];
        }
    }
    __syncthreads();   // H2 reads done; As region can be reused for es

    // ---- epilogue2: es (tf32, [64][36]) + act ------------------------------
    {
        const float fcab = fca_b[0];
#pragma unroll
        for (int mt = 0; mt < 2; mt++) {
            int r0 = m0 + mt * 16 + gr;
#pragma unroll
            for (int jj = 0; jj < 2; jj++) {
                int col = j0 + jj * 8 + 2 * tg;
                float* d = acc2[mt][jj];
                if (col < 32) {
                    float b0 = fcebS[col], b1 = fcebS[col + 1];
                    AsU[r0 * 36 + col]           = f2tf(d[0] + b0);
                    AsU[r0 * 36 + col + 1]       = f2tf(d[1] + b1);
                    AsU[(r0 + 8) * 36 + col]     = f2tf(d[2] + b0);
                    AsU[(r0 + 8) * 36 + col + 1] = f2tf(d[3] + b1);
                } else if (col == 32) {
                    actS[r0]     = sigmoidf_(d[0] + fcab);
                    actS[r0 + 8] = sigmoidf_(d[2] + fcab);
                }
            }
        }
    }
    __syncthreads();

    // ---- relation mma: M=64 n, N=256 v, K=32; B (vs) via LDG ---------------
    const int v0 = wn * 64;
    float accr[2][8][4] = {};
    {
        const uint32_t* vsp = g_vsf + (wn * 8) * 64 + lane * 2;
        uint2 curV[8], nxtV[8];
#pragma unroll
        for (int j = 0; j < 8; j++) curV[j] = *(const uint2*)(vsp + j * 64);
#pragma unroll
        for (int e8 = 0; e8 < 4; e8++) {
            if (e8 < 3) {
                const uint32_t* p = vsp + (e8 + 1) * 2048;
#pragma unroll
                for (int j = 0; j < 8; j++) nxtV[j] = *(const uint2*)(p + j * 64);
            }
            uint32_t aF[2][4];
#pragma unroll
            for (int mt = 0; mt < 2; mt++) {
                uint32_t adr = as_b + (uint32_t)(((m0 + mt * 16 + lr8 * 8 + l7) * 36
                                                  + e8 * 8 + lhi * 4) * 4);
                ldm_x4(aF[mt], adr);
            }
#pragma unroll
            for (int j = 0; j < 8; j++)
#pragma unroll
                for (int mt = 0; mt < 2; mt++)
                    mma8(accr[mt][j], aF[mt], (const uint32_t*)&curV[j]);
#pragma unroll
            for (int j = 0; j < 8; j++) curV[j] = nxtV[j];
        }
    }

    // ---- softmax (registers + small smem combines) -------------------------
#pragma unroll
    for (int mt = 0; mt < 2; mt++) {
        float mxa = -1e30f, mxb = -1e30f;
#pragma unroll
        for (int nt = 0; nt < 8; nt++) {
            float* d = accr[mt][nt];
            mxa = fmaxf(mxa, fmaxf(d[0], d[1]));
            mxb = fmaxf(mxb, fmaxf(d[2], d[3]));
        }
        mxa = fmaxf(mxa, __shfl_xor_sync(0xffffffffu, mxa, 1));
        mxa = fmaxf(mxa, __shfl_xor_sync(0xffffffffu, mxa, 2));
        mxb = fmaxf(mxb, __shfl_xor_sync(0xffffffffu, mxb, 1));
        mxb = fmaxf(mxb, __shfl_xor_sync(0xffffffffu, mxb, 2));
        if (tg == 0) {
            redm[(m0 + mt * 16 + gr) * 4 + wn] = mxa;
            redm[(m0 + mt * 16 + 8 + gr) * 4 + wn] = mxb;
        }
    }
    __syncthreads();

#pragma unroll
    for (int mt = 0; mt < 2; mt++) {
        int na = m0 + mt * 16 + gr, nb = na + 8;
        float ma = fmaxf(fmaxf(redm[na * 4 + 0], redm[na * 4 + 1]),
                         fmaxf(redm[na * 4 + 2], redm[na * 4 + 3]));
        float mb = fmaxf(fmaxf(redm[nb * 4 + 0], redm[nb * 4 + 1]),
                         fmaxf(redm[nb * 4 + 2], redm[nb * 4 + 3]));
        float sa = 0.f, sb = 0.f;
#pragma unroll
        for (int nt = 0; nt < 8; nt++) {
            float* d = accr[mt][nt];
            d[0] = __expf(d[0] - ma); d[1] = __expf(d[1] - ma);
            d[2] = __expf(d[2] - mb); d[3] = __expf(d[3] - mb);
            sa += d[0] + d[1];
            sb += d[2] + d[3];
        }
        sa += __shfl_xor_sync(0xffffffffu, sa, 1);
        sa += __shfl_xor_sync(0xffffffffu, sa, 2);
        sb += __shfl_xor_sync(0xffffffffu, sb, 1);
        sb += __shfl_xor_sync(0xffffffffu, sb, 2);
        if (tg == 0) { reds[na * 4 + wn] = sa; reds[nb * 4 + wn] = sb; }
    }
    __syncthreads();

    // scale + write route [64 n][260 v] into As region (es dead)
#pragma unroll
    for (int mt = 0; mt < 2; mt++) {
        int na = m0 + mt * 16 + gr, nb = na + 8;
        float sA = reds[na * 4 + 0] + reds[na * 4 + 1] + reds[na * 4 + 2] + reds[na * 4 + 3];
        float sB = reds[nb * 4 + 0] + reds[nb * 4 + 1] + reds[nb * 4 + 2] + reds[nb * 4 + 3];
        float scA = actS[na] / sA;
        float scB = actS[nb] / sB;
#pragma unroll
        for (int nt = 0; nt < 8; nt++) {
            int v = v0 + nt * 8 + 2 * tg;
            float* d = accr[mt][nt];
            uint2 ua, ub;
            ua.x = f2tf(d[0] * scA); ua.y = f2tf(d[1] * scA);
            ub.x = f2tf(d[2] * scB); ub.y = f2tf(d[3] * scB);
            *(uint2*)&AsU[na * 260 + v] = ua;
            *(uint2*)&AsU[nb * 260 + v] = ub;
        }
    }
    __syncthreads();

    // ---- out GEMM: out[c][n] = VC @ route, M=128 c, N=64 n, K=256; A via LDG
    const int wm2 = wid >> 1, wn2 = wid & 1;
    const int c0 = wm2 * 32, n0o = wn2 * 32;
    float acco[2][4][4] = {};
    {
        const uint32_t* vcp = g_vcf + ((size_t)(b * 32) * 8 + wm2 * 2) * 128 + lane * 4;
        uint4 curA[2], nxtA[2];
#pragma unroll
        for (int mt = 0; mt < 2; mt++) curA[mt] = *(const uint4*)(vcp + mt * 128);
        for (int v8 = 0; v8 < 32; v8++) {
            if (v8 < 31) {
                const uint32_t* p = vcp + (size_t)(v8 + 1) * 1024;
#pragma unroll
                for (int mt = 0; mt < 2; mt++) nxtA[mt] = *(const uint4*)(p + mt * 128);
            }
#pragma unroll
            for (int ntp = 0; ntp < 2; ntp++) {
                uint32_t bF[4];
                uint32_t adr = as_b + (uint32_t)(((n0o + (ntp * 2 + lhi) * 8 + l7) * 260
                                                  + v8 * 8 + lr8 * 4) * 4);
                ldm_x4(bF, adr);
#pragma unroll
                for (int mt = 0; mt < 2; mt++) {
                    mma8(acco[mt][2 * ntp],     (const uint32_t*)&curA[mt], bF);
                    mma8(acco[mt][2 * ntp + 1], (const uint32_t*)&curA[mt], bF + 2);
                }
            }
#pragma unroll
            for (int mt = 0; mt < 2; mt++) curA[mt] = nxtA[mt];
        }
    }

    // ---- store out ----
#pragma unroll
    for (int mt = 0; mt < 2; mt++) {
#pragma unroll
        for (int nt = 0; nt < 4; nt++) {
            int r0 = c0 + mt * 16 + gr;
            int ng = n0g + n0o + nt * 8 + 2 * tg;
            float* d = acco[mt][nt];
            if (ng < N_WRD) {
                float2 s0; s0.x = d[0]; s0.y = d[1];
                float2 s1; s1.x = d[2]; s1.y = d[3];
                *(float2*)&out[((size_t)b * CSZ + r0) * N_WRD + ng]     = s0;
                *(float2*)&out[((size_t)b * CSZ + r0 + 8) * N_WRD + ng] = s1;
            }
        }
    }
}

// ---------------- launch --------------------------------------------------
extern "C" void kernel_launch(void* const* d_in, const int* in_sizes, int n_in,
                              void* d_out, int out_size) {
    const float* view_cell = (const float*)d_in[0];
    const float* v         = (const float*)d_in[1];
    const float* w2c_w1    = (const float*)d_in[2];
    const float* w2c_b1    = (const float*)d_in[3];
    const float* w2c_w2    = (const float*)d_in[4];
    const float* w2c_b2    = (const float*)d_in[5];
    const float* fc1_w     = (const float*)d_in[6];
    const float* fc1_b     = (const float*)d_in[7];
    const float* fc2_w     = (const float*)d_in[8];
    const float* fc2_b     = (const float*)d_in[9];
    const float* fca_w     = (const float*)d_in[10];
    const float* fca_b     = (const float*)d_in[11];
    const float* fce_w     = (const float*)d_in[12];
    const float* fce_b     = (const float*)d_in[13];
    const float* vse_w1    = (const float*)d_in[14];
    const float* vse_b1    = (const float*)d_in[15];
    const float* vse_w2    = (const float*)d_in[16];
    const float* vse_b2    = (const float*)d_in[17];
    float* out = (float*)d_out;

    static bool attr_set = false;
    if (!attr_set) {
        cudaFuncSetAttribute(k_AB, cudaFuncAttributeMaxDynamicSharedMemorySize, KF_TOT * 4);
        attr_set = true;
    }

    k_setup<<<2494, 256>>>(fc2_w, fce_w, fca_w, view_cell, v, w2c_w1, w2c_b1,
                           w2c_w2, w2c_b2, vse_w1, vse_b1, vse_w2, vse_b2);
    dim3 gridF((N_WRD + 63) / 64, B_SZ);
    k_AB<<<gridF, 256, KF_TOT * 4>>>(fc1_w, fc1_b, fc2_b, fca_b, fce_b, out);
}

// round 11
// speedup vs baseline: 1.5910x; 1.2320x over previous
#include <cuda_runtime.h>
#include <cuda_fp16.h>
#include <cstdint>

#define N_WRD  2000
#define B_SZ   64
#define CSZ    128
#define V_PIX  256
#define EMB    32

// ---------------- scratch (device globals; no allocations allowed) ----------
__device__ float    g_wcode[B_SZ * 6000 + 192];          // padded for tile overrun
__device__ uint32_t g_w2f16[16 * 32 * 64];               // W2 fp16 B-frags [k16][n8][64]
__device__ uint32_t g_we2f16[16 * 8 * 64];               // We2 fp16 B-frags [k16][j8][64]
__device__ uint32_t g_vsf16[2 * 32 * 64];                // vs fp16 B-frags [e16][v8][64]
__device__ uint32_t g_vcf[(size_t)B_SZ * 32 * 8 * 128];  // VC tf32 A-frags [b][v8][c16][128]

// ============================ helpers =======================================
__device__ __forceinline__ uint32_t f2tf(float f) {
    uint32_t u; asm("cvt.rna.tf32.f32 %0, %1;" : "=r"(u) : "f"(f)); return u;
}
__device__ __forceinline__ uint32_t pack_h2(float lo, float hi) {
    __half2 h = __floats2half2_rn(lo, hi);
    return *(uint32_t*)&h;
}
__device__ __forceinline__ void mma8(float* d, const uint32_t* a, const uint32_t* b) {
    asm volatile("mma.sync.aligned.m16n8k8.row.col.f32.tf32.tf32.f32 "
        "{%0,%1,%2,%3}, {%4,%5,%6,%7}, {%8,%9}, {%0,%1,%2,%3};"
        : "+f"(d[0]), "+f"(d[1]), "+f"(d[2]), "+f"(d[3])
        : "r"(a[0]), "r"(a[1]), "r"(a[2]), "r"(a[3]), "r"(b[0]), "r"(b[1]));
}
__device__ __forceinline__ void mma16(float* d, const uint32_t* a, const uint32_t* b) {
    asm volatile("mma.sync.aligned.m16n8k16.row.col.f32.f16.f16.f32 "
        "{%0,%1,%2,%3}, {%4,%5,%6,%7}, {%8,%9}, {%0,%1,%2,%3};"
        : "+f"(d[0]), "+f"(d[1]), "+f"(d[2]), "+f"(d[3])
        : "r"(a[0]), "r"(a[1]), "r"(a[2]), "r"(a[3]), "r"(b[0]), "r"(b[1]));
}
__device__ __forceinline__ void ldm_x4(uint32_t* r, uint32_t addr) {
    asm volatile("ldmatrix.sync.aligned.m8n8.x4.shared.b16 {%0,%1,%2,%3}, [%4];"
        : "=r"(r[0]), "=r"(r[1]), "=r"(r[2]), "=r"(r[3]) : "r"(addr));
}
__device__ __forceinline__ uint32_t smem_u32(const void* p) {
    uint32_t a;
    asm("{ .reg .u64 t; cvta.to.shared.u64 t, %1; cvt.u32.u64 %0, t; }"
        : "=r"(a) : "l"(p));
    return a;
}
__device__ __forceinline__ float sigmoidf_(float x) {
    return 1.f / (1.f + __expf(-x));
}

// ====== setup kernel ========================================================
// blocks: [0,128) w2f16 | [128,160) we2f16 | [160,176) vsf16 | [176,2224) vcf
//         [2224,2318) wcode
__global__ __launch_bounds__(256) void k_setup(
    const float* __restrict__ fc2_w, const float* __restrict__ fce_w,
    const float* __restrict__ fca_w, const float* __restrict__ vc_g,
    const float* __restrict__ v, const float* __restrict__ w2c_w1,
    const float* __restrict__ w2c_b1,
    const float* __restrict__ w2c_w2, const float* __restrict__ w2c_b2,
    const float* __restrict__ vse_w1, const float* __restrict__ vse_b1,
    const float* __restrict__ vse_w2, const float* __restrict__ vse_b2) {
    const int bid = blockIdx.x;
    const int t = threadIdx.x;
    if (bid < 128) {
        // W2 fp16 B-frags: halves {W2[k0][n], W2[k0+1][n]}
        int idx = bid * 256 + t;
        int k16 = idx >> 11, rem = idx & 2047;
        int n8 = rem >> 6, w = rem & 63;
        int lane = w >> 1, h = w & 1;
        int k0 = k16 * 16 + (lane & 3) * 2 + h * 8;
        int n  = n8 * 8 + (lane >> 2);
        g_w2f16[idx] = pack_h2(fc2_w[k0 * 256 + n], fc2_w[(k0 + 1) * 256 + n]);
    } else if (bid < 160) {
        int idx = (bid - 128) * 256 + t;
        int k16 = idx >> 9, rem = idx & 511;
        int j8 = rem >> 6, w = rem & 63;
        int lane = w >> 1, h = w & 1;
        int k0 = k16 * 16 + (lane & 3) * 2 + h * 8;
        int j = j8 * 8 + (lane >> 2);
        float v0 = (j < 32) ? fce_w[k0 * 32 + j] : ((j == 32) ? fca_w[k0] : 0.f);
        float v1 = (j < 32) ? fce_w[(k0 + 1) * 32 + j] : ((j == 32) ? fca_w[k0 + 1] : 0.f);
        g_we2f16[idx] = pack_h2(v0, v1);
    } else if (bid < 176) {
        // vs fp16 B-frags: halves {vs[v][e0], vs[v][e0+1]}
        int idx = (bid - 160) * 256 + t;
        int e16 = idx >> 11, rem = idx & 2047;
        int v8 = rem >> 6, w = rem & 63;
        int lane = w >> 1, h = w & 1;
        int vv = v8 * 8 + (lane >> 2);
        int e0 = e16 * 16 + (lane & 3) * 2 + h * 8;
        float x = -1.f + (2.f / 15.f) * (float)(vv >> 4);
        float y = -1.f + (2.f / 15.f) * (float)(vv & 15);
        float a0 = vse_b2[e0], a1 = vse_b2[e0 + 1];
#pragma unroll 4
        for (int j = 0; j < 128; j++) {
            float hh = fmaxf(fmaf(x, vse_w1[j], fmaf(y, vse_w1[128 + j], vse_b1[j])), 0.f);
            a0 = fmaf(hh, vse_w2[j * EMB + e0], a0);
            a1 = fmaf(hh, vse_w2[j * EMB + e0 + 1], a1);
        }
        g_vsf16[idx] = pack_h2(a0, a1);
    } else if (bid < 2224) {
        // VC tf32 A-frags
        int blk = bid - 176;
        int b = blk >> 5, v8 = blk & 31;
        for (int i = t; i < 1024; i += 256) {
            int c16 = i >> 7, w = i & 127;
            int l = w >> 2, q = w & 3;
            int c = c16 * 16 + (l >> 2) + (q & 1) * 8;
            int vv = v8 * 8 + (l & 3) + (q >> 1) * 4;
            g_vcf[((size_t)(b * 32 + v8) * 8 + c16) * 128 + w] =
                f2tf(vc_g[((size_t)b * CSZ + c) * V_PIX + vv]);
        }
    } else {
        // ---- wcode tile ----
        __shared__ float As[64 * 33];
        __shared__ float Bs[32 * 68];
        __shared__ float vS[448];
        int tx = t & 15, ty = t >> 4;
        int n0 = (bid - 2224) * 64;
        for (int i = t; i < 448; i += 256) vS[i] = v[i];
        __syncthreads();
        float acc[4][4] = {};
        for (int k0 = 0; k0 < 512; k0 += 32) {
            for (int i = t; i < 2048; i += 256) {
                int r = i >> 5, k = i & 31;
                int kk = k0 + k;
                float a = w2c_b1[kk];
#pragma unroll
                for (int q = 0; q < 7; q++)
                    a = fmaf(vS[r * 7 + q], w2c_w1[q * 512 + kk], a);
                As[r * 33 + k] = fmaxf(a, 0.f);
            }
            for (int i = t; i < 2048; i += 256) {
                int k = i >> 6, n = i & 63;
                int nn = n0 + n;
                Bs[k * 68 + n] = (nn < 6000) ? w2c_w2[(k0 + k) * 6000 + nn] : 0.f;
            }
            __syncthreads();
#pragma unroll
            for (int k = 0; k < 32; k++) {
                float a[4], bb[4];
#pragma unroll
                for (int i = 0; i < 4; i++) a[i] = As[(4 * ty + i) * 33 + k];
#pragma unroll
                for (int j = 0; j < 4; j++) bb[j] = Bs[k * 68 + 4 * tx + j];
#pragma unroll
                for (int i = 0; i < 4; i++)
#pragma unroll
                    for (int j = 0; j < 4; j++) acc[i][j] = fmaf(a[i], bb[j], acc[i][j]);
            }
            __syncthreads();
        }
#pragma unroll
        for (int i = 0; i < 4; i++) {
            int r = 4 * ty + i;
#pragma unroll
            for (int j = 0; j < 4; j++) {
                int col = n0 + 4 * tx + j;
                if (col < 6000) g_wcode[r * 6000 + col] = acc[i][j] + w2c_b2[col];
            }
        }
    }
}

// ====== fused kernel ========================================================
// smem words: As region [0,16640): A/H2 fp16 [64][264 halves]=8448w, es fp16
//             [64][40 halves]=1280w, route tf32 [64][260]=16640w (phase-disjoint)
#define KF_AS    0
#define KF_ACT   16640      // 64
#define KF_RM    16704      // 256
#define KF_RS    16960      // 256
#define KF_FC2B  17216      // 256
#define KF_FCEB  17472      // 32
#define KF_WC    17504      // 192
#define KF_TOT   17696      // -> 70784 bytes

__global__ __launch_bounds__(256, 2) void k_AB(
    const float* __restrict__ fc1_w, const float* __restrict__ fc1_b,
    const float* __restrict__ fc2_b,
    const float* __restrict__ fca_b, const float* __restrict__ fce_b,
    float* __restrict__ out) {
    extern __shared__ float sm[];
    uint32_t* AsU  = (uint32_t*)sm;
    float*    actS = sm + KF_ACT;
    float*    redm = sm + KF_RM;
    float*    reds = sm + KF_RS;
    float*    fc2bS= sm + KF_FC2B;
    float*    fcebS= sm + KF_FCEB;
    float*    wcS  = sm + KF_WC;

    const uint32_t as_b = smem_u32(sm);

    const int t = threadIdx.x;
    const int wid = t >> 5, lane = t & 31;
    const int gr = lane >> 2, tg = lane & 3;
    const int lr8 = (lane >> 3) & 1, l7 = lane & 7, lhi = lane >> 4;
    const int n0g = blockIdx.x * 64;
    const int b   = blockIdx.y;
    const int row0g = b * N_WRD + n0g;

    // ---- consts + wcode rows ----
    fc2bS[t] = fc2_b[t];
    if (t < 32) fcebS[t] = fce_b[t];
    if (t < 192) wcS[t] = g_wcode[row0g * 3 + t];
    __syncthreads();

    // ---- fc1 -> As fp16 ([64 rows][264 halves], word stride 132) ----
    {
        int r = t >> 2, kb = (t & 3) * 64;
        float w0 = wcS[r * 3 + 0], w1 = wcS[r * 3 + 1], w2 = wcS[r * 3 + 2];
        for (int k = kb; k < kb + 64; k += 4) {
            float a0 = fmaxf(fmaf(w0, fc1_w[k+0], fmaf(w1, fc1_w[256+k+0], fmaf(w2, fc1_w[512+k+0], fc1_b[k+0]))), 0.f);
            float a1 = fmaxf(fmaf(w0, fc1_w[k+1], fmaf(w1, fc1_w[256+k+1], fmaf(w2, fc1_w[512+k+1], fc1_b[k+1]))), 0.f);
            float a2 = fmaxf(fmaf(w0, fc1_w[k+2], fmaf(w1, fc1_w[256+k+2], fmaf(w2, fc1_w[512+k+2], fc1_b[k+2]))), 0.f);
            float a3 = fmaxf(fmaf(w0, fc1_w[k+3], fmaf(w1, fc1_w[256+k+3], fmaf(w2, fc1_w[512+k+3], fc1_b[k+3]))), 0.f);
            uint2 u; u.x = pack_h2(a0, a1); u.y = pack_h2(a2, a3);
            *(uint2*)&AsU[r * 132 + (k >> 1)] = u;
        }
    }
    __syncthreads();

    // ---- MMA1 (fp16): H2raw = A @ W2 (64x256, K=256). warps 2m x 4n --------
    const int wm = wid & 1, wn = wid >> 1;
    const int m0 = wm * 32, n0 = wn * 64;
    {
        const uint32_t* w2p = g_w2f16 + (wn * 8) * 64 + lane * 2;
        uint2 curB[8], nxtB[8];
#pragma unroll
        for (int j = 0; j < 8; j++) curB[j] = *(const uint2*)(w2p + j * 64);
        float acc1[2][8][4] = {};
        for (int k16 = 0; k16 < 16; k16++) {
            if (k16 < 15) {
                const uint32_t* p = w2p + (k16 + 1) * 2048;
#pragma unroll
                for (int j = 0; j < 8; j++) nxtB[j] = *(const uint2*)(p + j * 64);
            }
            uint32_t aF[2][4];
#pragma unroll
            for (int mt = 0; mt < 2; mt++) {
                uint32_t adr = as_b + (uint32_t)((m0 + mt * 16 + lr8 * 8 + l7) * 528
                                                  + k16 * 32 + lhi * 16);
                ldm_x4(aF[mt], adr);
            }
#pragma unroll
            for (int j = 0; j < 8; j++)
#pragma unroll
                for (int mt = 0; mt < 2; mt++)
                    mma16(acc1[mt][j], aF[mt], (const uint32_t*)&curB[j]);
#pragma unroll
            for (int j = 0; j < 8; j++) curB[j] = nxtB[j];
        }
        __syncthreads();   // all MMA1 reads of As done

        // epilogue1: H2 = relu(acc + bias) -> As fp16 (same region)
#pragma unroll
        for (int mt = 0; mt < 2; mt++) {
#pragma unroll
            for (int nt = 0; nt < 8; nt++) {
                int col = n0 + nt * 8 + 2 * tg;
                int r0 = m0 + mt * 16 + gr;
                float b0 = fc2bS[col], b1 = fc2bS[col + 1];
                float* d = acc1[mt][nt];
                AsU[r0 * 132 + (col >> 1)] =
                    pack_h2(fmaxf(d[0] + b0, 0.f), fmaxf(d[1] + b1, 0.f));
                AsU[(r0 + 8) * 132 + (col >> 1)] =
                    pack_h2(fmaxf(d[2] + b0, 0.f), fmaxf(d[3] + b1, 0.f));
            }
        }
    }
    __syncthreads();

    // ---- MMA2 (fp16): D2 = H2 @ We2 (64x64, K=256) -------------------------
    const int j0 = wn * 16;
    float acc2[2][2][4] = {};
    {
        const uint32_t* wep = g_we2f16 + (wn * 2) * 64 + lane * 2;
        uint2 curW[2], nxtW[2];
#pragma unroll
        for (int jj = 0; jj < 2; jj++) curW[jj] = *(const uint2*)(wep + jj * 64);
        for (int k16 = 0; k16 < 16; k16++) {
            if (k16 < 15) {
                const uint32_t* p = wep + (k16 + 1) * 512;
#pragma unroll
                for (int jj = 0; jj < 2; jj++) nxtW[jj] = *(const uint2*)(p + jj * 64);
            }
            uint32_t aF[2][4];
#pragma unroll
            for (int mt = 0; mt < 2; mt++) {
                uint32_t adr = as_b + (uint32_t)((m0 + mt * 16 + lr8 * 8 + l7) * 528
                                                  + k16 * 32 + lhi * 16);
                ldm_x4(aF[mt], adr);
            }
#pragma unroll
            for (int jj = 0; jj < 2; jj++)
#pragma unroll
                for (int mt = 0; mt < 2; mt++)
                    mma16(acc2[mt][jj], aF[mt], (const uint32_t*)&curW[jj]);
#pragma unroll
            for (int jj = 0; jj < 2; jj++) curW[jj] = nxtW[jj];
        }
    }
    __syncthreads();   // H2 reads done; As region reused for es

    // ---- epilogue2: es fp16 ([64][40 halves], word stride 20) + act --------
    {
        const float fcab = fca_b[0];
#pragma unroll
        for (int mt = 0; mt < 2; mt++) {
            int r0 = m0 + mt * 16 + gr;
#pragma unroll
            for (int jj = 0; jj < 2; jj++) {
                int col = j0 + jj * 8 + 2 * tg;
                float* d = acc2[mt][jj];
                if (col < 32) {
                    float b0 = fcebS[col], b1 = fcebS[col + 1];
                    AsU[r0 * 20 + (col >> 1)]       = pack_h2(d[0] + b0, d[1] + b1);
                    AsU[(r0 + 8) * 20 + (col >> 1)] = pack_h2(d[2] + b0, d[3] + b1);
                } else if (col == 32) {
                    actS[r0]     = sigmoidf_(d[0] + fcab);
                    actS[r0 + 8] = sigmoidf_(d[2] + fcab);
                }
            }
        }
    }
    __syncthreads();

    // ---- relation (fp16): M=64 n, N=256 v, K=32 ----------------------------
    const int v0 = wn * 64;
    float accr[2][8][4] = {};
    {
        const uint32_t* vsp = g_vsf16 + (wn * 8) * 64 + lane * 2;
        uint2 curV[8], nxtV[8];
#pragma unroll
        for (int j = 0; j < 8; j++) curV[j] = *(const uint2*)(vsp + j * 64);
#pragma unroll
        for (int e16 = 0; e16 < 2; e16++) {
            if (e16 < 1) {
                const uint32_t* p = vsp + 2048;
#pragma unroll
                for (int j = 0; j < 8; j++) nxtV[j] = *(const uint2*)(p + j * 64);
            }
            uint32_t aF[2][4];
#pragma unroll
            for (int mt = 0; mt < 2; mt++) {
                uint32_t adr = as_b + (uint32_t)((m0 + mt * 16 + lr8 * 8 + l7) * 80
                                                  + e16 * 32 + lhi * 16);
                ldm_x4(aF[mt], adr);
            }
#pragma unroll
            for (int j = 0; j < 8; j++)
#pragma unroll
                for (int mt = 0; mt < 2; mt++)
                    mma16(accr[mt][j], aF[mt], (const uint32_t*)&curV[j]);
#pragma unroll
            for (int j = 0; j < 8; j++) curV[j] = nxtV[j];
        }
    }

    // ---- softmax (registers + small smem combines) -------------------------
#pragma unroll
    for (int mt = 0; mt < 2; mt++) {
        float mxa = -1e30f, mxb = -1e30f;
#pragma unroll
        for (int nt = 0; nt < 8; nt++) {
            float* d = accr[mt][nt];
            mxa = fmaxf(mxa, fmaxf(d[0], d[1]));
            mxb = fmaxf(mxb, fmaxf(d[2], d[3]));
        }
        mxa = fmaxf(mxa, __shfl_xor_sync(0xffffffffu, mxa, 1));
        mxa = fmaxf(mxa, __shfl_xor_sync(0xffffffffu, mxa, 2));
        mxb = fmaxf(mxb, __shfl_xor_sync(0xffffffffu, mxb, 1));
        mxb = fmaxf(mxb, __shfl_xor_sync(0xffffffffu, mxb, 2));
        if (tg == 0) {
            redm[(m0 + mt * 16 + gr) * 4 + wn] = mxa;
            redm[(m0 + mt * 16 + 8 + gr) * 4 + wn] = mxb;
        }
    }
    __syncthreads();   // es reads complete; redm visible

#pragma unroll
    for (int mt = 0; mt < 2; mt++) {
        int na = m0 + mt * 16 + gr, nb = na + 8;
        float ma = fmaxf(fmaxf(redm[na * 4 + 0], redm[na * 4 + 1]),
                         fmaxf(redm[na * 4 + 2], redm[na * 4 + 3]));
        float mb = fmaxf(fmaxf(redm[nb * 4 + 0], redm[nb * 4 + 1]),
                         fmaxf(redm[nb * 4 + 2], redm[nb * 4 + 3]));
        float sa = 0.f, sb = 0.f;
#pragma unroll
        for (int nt = 0; nt < 8; nt++) {
            float* d = accr[mt][nt];
            d[0] = __expf(d[0] - ma); d[1] = __expf(d[1] - ma);
            d[2] = __expf(d[2] - mb); d[3] = __expf(d[3] - mb);
            sa += d[0] + d[1];
            sb += d[2] + d[3];
        }
        sa += __shfl_xor_sync(0xffffffffu, sa, 1);
        sa += __shfl_xor_sync(0xffffffffu, sa, 2);
        sb += __shfl_xor_sync(0xffffffffu, sb, 1);
        sb += __shfl_xor_sync(0xffffffffu, sb, 2);
        if (tg == 0) { reds[na * 4 + wn] = sa; reds[nb * 4 + wn] = sb; }
    }
    __syncthreads();

    // scale + write route tf32 [64 n][260 v] into As region (es dead)
#pragma unroll
    for (int mt = 0; mt < 2; mt++) {
        int na = m0 + mt * 16 + gr, nb = na + 8;
        float sA = reds[na * 4 + 0] + reds[na * 4 + 1] + reds[na * 4 + 2] + reds[na * 4 + 3];
        float sB = reds[nb * 4 + 0] + reds[nb * 4 + 1] + reds[nb * 4 + 2] + reds[nb * 4 + 3];
        float scA = actS[na] / sA;
        float scB = actS[nb] / sB;
#pragma unroll
        for (int nt = 0; nt < 8; nt++) {
            int v = v0 + nt * 8 + 2 * tg;
            float* d = accr[mt][nt];
            uint2 ua, ub;
            ua.x = f2tf(d[0] * scA); ua.y = f2tf(d[1] * scA);
            ub.x = f2tf(d[2] * scB); ub.y = f2tf(d[3] * scB);
            *(uint2*)&AsU[na * 260 + v] = ua;
            *(uint2*)&AsU[nb * 260 + v] = ub;
        }
    }
    __syncthreads();

    // ---- out GEMM (tf32): out[c][n] = VC @ route, M=128, N=64, K=256 -------
    const int wm2 = wid >> 1, wn2 = wid & 1;
    const int c0 = wm2 * 32, n0o = wn2 * 32;
    float acco[2][4][4] = {};
    {
        const uint32_t* vcp = g_vcf + ((size_t)(b * 32) * 8 + wm2 * 2) * 128 + lane * 4;
        uint4 curA[2], nxtA[2];
#pragma unroll
        for (int mt = 0; mt < 2; mt++) curA[mt] = *(const uint4*)(vcp + mt * 128);
        for (int v8 = 0; v8 < 32; v8++) {
            if (v8 < 31) {
                const uint32_t* p = vcp + (size_t)(v8 + 1) * 1024;
#pragma unroll
                for (int mt = 0; mt < 2; mt++) nxtA[mt] = *(const uint4*)(p + mt * 128);
            }
#pragma unroll
            for (int ntp = 0; ntp < 2; ntp++) {
                uint32_t bF[4];
                uint32_t adr = as_b + (uint32_t)(((n0o + (ntp * 2 + lhi) * 8 + l7) * 260
                                                  + v8 * 8 + lr8 * 4) * 4);
                ldm_x4(bF, adr);
#pragma unroll
                for (int mt = 0; mt < 2; mt++) {
                    mma8(acco[mt][2 * ntp],     (const uint32_t*)&curA[mt], bF);
                    mma8(acco[mt][2 * ntp + 1], (const uint32_t*)&curA[mt], bF + 2);
                }
            }
#pragma unroll
            for (int mt = 0; mt < 2; mt++) curA[mt] = nxtA[mt];
        }
    }

    // ---- store out ----
#pragma unroll
    for (int mt = 0; mt < 2; mt++) {
#pragma unroll
        for (int nt = 0; nt < 4; nt++) {
            int r0 = c0 + mt * 16 + gr;
            int ng = n0g + n0o + nt * 8 + 2 * tg;
            float* d = acco[mt][nt];
            if (ng < N_WRD) {
                float2 s0; s0.x = d[0]; s0.y = d[1];
                float2 s1; s1.x = d[2]; s1.y = d[3];
                *(float2*)&out[((size_t)b * CSZ + r0) * N_WRD + ng]     = s0;
                *(float2*)&out[((size_t)b * CSZ + r0 + 8) * N_WRD + ng] = s1;
            }
        }
    }
}

// ---------------- launch --------------------------------------------------
extern "C" void kernel_launch(void* const* d_in, const int* in_sizes, int n_in,
                              void* d_out, int out_size) {
    const float* view_cell = (const float*)d_in[0];
    const float* v         = (const float*)d_in[1];
    const float* w2c_w1    = (const float*)d_in[2];
    const float* w2c_b1    = (const float*)d_in[3];
    const float* w2c_w2    = (const float*)d_in[4];
    const float* w2c_b2    = (const float*)d_in[5];
    const float* fc1_w     = (const float*)d_in[6];
    const float* fc1_b     = (const float*)d_in[7];
    const float* fc2_w     = (const float*)d_in[8];
    const float* fc2_b     = (const float*)d_in[9];
    const float* fca_w     = (const float*)d_in[10];
    const float* fca_b     = (const float*)d_in[11];
    const float* fce_w     = (const float*)d_in[12];
    const float* fce_b     = (const float*)d_in[13];
    const float* vse_w1    = (const float*)d_in[14];
    const float* vse_b1    = (const float*)d_in[15];
    const float* vse_w2    = (const float*)d_in[16];
    const float* vse_b2    = (const float*)d_in[17];
    float* out = (float*)d_out;

    static bool attr_set = false;
    if (!attr_set) {
        cudaFuncSetAttribute(k_AB, cudaFuncAttributeMaxDynamicSharedMemorySize, KF_TOT * 4);
        attr_set = true;
    }

    k_setup<<<2318, 256>>>(fc2_w, fce_w, fca_w, view_cell, v, w2c_w1, w2c_b1,
                           w2c_w2, w2c_b2, vse_w1, vse_b1, vse_w2, vse_b2);
    dim3 gridF((N_WRD + 63) / 64, B_SZ);
    k_AB<<<gridF, 256, KF_TOT * 4>>>(fc1_w, fc1_b, fc2_b, fca_b, fce_b, out);
}

// round 12
// speedup vs baseline: 1.8578x; 1.1677x over previous
#include <cuda_runtime.h>
#include <cuda_fp16.h>
#include <cstdint>

#define N_WRD  2000
#define B_SZ   64
#define CSZ    128
#define V_PIX  256
#define EMB    32

// ---------------- scratch (device globals; no allocations allowed) ----------
__device__ float    g_wcode[B_SZ * 6000 + 192];            // padded for tile overrun
__device__ uint32_t g_w2f16[16 * 32 * 64];                 // W2 fp16 B-frags [k16][n8][64]
__device__ uint32_t g_we2f16[16 * 8 * 64];                 // We2 fp16 B-frags [k16][j8][64]
__device__ uint32_t g_vsf16[2 * 32 * 64];                  // vs fp16 B-frags [e16][v8][64]
__device__ uint32_t g_vcf16[(size_t)B_SZ * 16 * 8 * 128];  // VC fp16 A-frags [b][v16][c16][128]

// ============================ helpers =======================================
__device__ __forceinline__ uint32_t pack_h2(float lo, float hi) {
    __half2 h = __floats2half2_rn(lo, hi);
    return *(uint32_t*)&h;
}
__device__ __forceinline__ void mma16(float* d, const uint32_t* a, const uint32_t* b) {
    asm volatile("mma.sync.aligned.m16n8k16.row.col.f32.f16.f16.f32 "
        "{%0,%1,%2,%3}, {%4,%5,%6,%7}, {%8,%9}, {%0,%1,%2,%3};"
        : "+f"(d[0]), "+f"(d[1]), "+f"(d[2]), "+f"(d[3])
        : "r"(a[0]), "r"(a[1]), "r"(a[2]), "r"(a[3]), "r"(b[0]), "r"(b[1]));
}
__device__ __forceinline__ void ldm_x4(uint32_t* r, uint32_t addr) {
    asm volatile("ldmatrix.sync.aligned.m8n8.x4.shared.b16 {%0,%1,%2,%3}, [%4];"
        : "=r"(r[0]), "=r"(r[1]), "=r"(r[2]), "=r"(r[3]) : "r"(addr));
}
__device__ __forceinline__ uint32_t smem_u32(const void* p) {
    uint32_t a;
    asm("{ .reg .u64 t; cvta.to.shared.u64 t, %1; cvt.u32.u64 %0, t; }"
        : "=r"(a) : "l"(p));
    return a;
}
__device__ __forceinline__ float sigmoidf_(float x) {
    return 1.f / (1.f + __expf(-x));
}

// ====== setup kernel ========================================================
// blocks: [0,128) w2f16 | [128,160) we2f16 | [160,176) vsf16 | [176,1200) vcf16
//         [1200,1294) wcode
__global__ __launch_bounds__(256) void k_setup(
    const float* __restrict__ fc2_w, const float* __restrict__ fce_w,
    const float* __restrict__ fca_w, const float* __restrict__ vc_g,
    const float* __restrict__ v, const float* __restrict__ w2c_w1,
    const float* __restrict__ w2c_b1,
    const float* __restrict__ w2c_w2, const float* __restrict__ w2c_b2,
    const float* __restrict__ vse_w1, const float* __restrict__ vse_b1,
    const float* __restrict__ vse_w2, const float* __restrict__ vse_b2) {
    const int bid = blockIdx.x;
    const int t = threadIdx.x;
    if (bid < 128) {
        int idx = bid * 256 + t;
        int k16 = idx >> 11, rem = idx & 2047;
        int n8 = rem >> 6, w = rem & 63;
        int lane = w >> 1, h = w & 1;
        int k0 = k16 * 16 + (lane & 3) * 2 + h * 8;
        int n  = n8 * 8 + (lane >> 2);
        g_w2f16[idx] = pack_h2(fc2_w[k0 * 256 + n], fc2_w[(k0 + 1) * 256 + n]);
    } else if (bid < 160) {
        int idx = (bid - 128) * 256 + t;
        int k16 = idx >> 9, rem = idx & 511;
        int j8 = rem >> 6, w = rem & 63;
        int lane = w >> 1, h = w & 1;
        int k0 = k16 * 16 + (lane & 3) * 2 + h * 8;
        int j = j8 * 8 + (lane >> 2);
        float v0 = (j < 32) ? fce_w[k0 * 32 + j] : ((j == 32) ? fca_w[k0] : 0.f);
        float v1 = (j < 32) ? fce_w[(k0 + 1) * 32 + j] : ((j == 32) ? fca_w[k0 + 1] : 0.f);
        g_we2f16[idx] = pack_h2(v0, v1);
    } else if (bid < 176) {
        int idx = (bid - 160) * 256 + t;
        int e16 = idx >> 11, rem = idx & 2047;
        int v8 = rem >> 6, w = rem & 63;
        int lane = w >> 1, h = w & 1;
        int vv = v8 * 8 + (lane >> 2);
        int e0 = e16 * 16 + (lane & 3) * 2 + h * 8;
        float x = -1.f + (2.f / 15.f) * (float)(vv >> 4);
        float y = -1.f + (2.f / 15.f) * (float)(vv & 15);
        float a0 = vse_b2[e0], a1 = vse_b2[e0 + 1];
#pragma unroll 4
        for (int j = 0; j < 128; j++) {
            float hh = fmaxf(fmaf(x, vse_w1[j], fmaf(y, vse_w1[128 + j], vse_b1[j])), 0.f);
            a0 = fmaf(hh, vse_w2[j * EMB + e0], a0);
            a1 = fmaf(hh, vse_w2[j * EMB + e0 + 1], a1);
        }
        g_vsf16[idx] = pack_h2(a0, a1);
    } else if (bid < 1200) {
        // VC fp16 A-frags: per block = (b, v16)
        // a0={A[c][v0],A[c][v0+1]} a1=row+8 a2=v+8 a3=both; c=c16*16+(lane>>2)
        int blk = bid - 176;
        int b = blk >> 4, v16 = blk & 15;
        for (int i = t; i < 1024; i += 256) {
            int c16 = i >> 7, w = i & 127;
            int lane = w >> 2, q = w & 3;
            int c = c16 * 16 + (lane >> 2) + (q & 1) * 8;
            int v0 = v16 * 16 + 2 * (lane & 3) + (q >> 1) * 8;
            const float* src = &vc_g[((size_t)b * CSZ + c) * V_PIX + v0];
            g_vcf16[((size_t)(b * 16 + v16) * 8 + c16) * 128 + w] =
                pack_h2(src[0], src[1]);
        }
    } else {
        // ---- wcode tile ----
        __shared__ float As[64 * 33];
        __shared__ float Bs[32 * 68];
        __shared__ float vS[448];
        int tx = t & 15, ty = t >> 4;
        int n0 = (bid - 1200) * 64;
        for (int i = t; i < 448; i += 256) vS[i] = v[i];
        __syncthreads();
        float acc[4][4] = {};
        for (int k0 = 0; k0 < 512; k0 += 32) {
            for (int i = t; i < 2048; i += 256) {
                int r = i >> 5, k = i & 31;
                int kk = k0 + k;
                float a = w2c_b1[kk];
#pragma unroll
                for (int q = 0; q < 7; q++)
                    a = fmaf(vS[r * 7 + q], w2c_w1[q * 512 + kk], a);
                As[r * 33 + k] = fmaxf(a, 0.f);
            }
            for (int i = t; i < 2048; i += 256) {
                int k = i >> 6, n = i & 63;
                int nn = n0 + n;
                Bs[k * 68 + n] = (nn < 6000) ? w2c_w2[(k0 + k) * 6000 + nn] : 0.f;
            }
            __syncthreads();
#pragma unroll
            for (int k = 0; k < 32; k++) {
                float a[4], bb[4];
#pragma unroll
                for (int i = 0; i < 4; i++) a[i] = As[(4 * ty + i) * 33 + k];
#pragma unroll
                for (int j = 0; j < 4; j++) bb[j] = Bs[k * 68 + 4 * tx + j];
#pragma unroll
                for (int i = 0; i < 4; i++)
#pragma unroll
                    for (int j = 0; j < 4; j++) acc[i][j] = fmaf(a[i], bb[j], acc[i][j]);
            }
            __syncthreads();
        }
#pragma unroll
        for (int i = 0; i < 4; i++) {
            int r = 4 * ty + i;
#pragma unroll
            for (int j = 0; j < 4; j++) {
                int col = n0 + 4 * tx + j;
                if (col < 6000) g_wcode[r * 6000 + col] = acc[i][j] + w2c_b2[col];
            }
        }
    }
}

// ====== fused kernel ========================================================
// smem words: As region [0,8448): A/H2 fp16 [64][264 halves], es fp16 [64][40h],
//             route fp16 [64][264 halves] (phase-disjoint)
#define KF_AS    0
#define KF_ACT   8448       // 64
#define KF_RM    8512       // 256
#define KF_RS    8768       // 256
#define KF_FC2B  9024       // 256
#define KF_FCEB  9280       // 32
#define KF_WC    9312       // 192
#define KF_TOT   9504       // -> 38016 bytes

__global__ __launch_bounds__(256, 2) void k_AB(
    const float* __restrict__ fc1_w, const float* __restrict__ fc1_b,
    const float* __restrict__ fc2_b,
    const float* __restrict__ fca_b, const float* __restrict__ fce_b,
    float* __restrict__ out) {
    extern __shared__ float sm[];
    uint32_t* AsU  = (uint32_t*)sm;
    float*    actS = sm + KF_ACT;
    float*    redm = sm + KF_RM;
    float*    reds = sm + KF_RS;
    float*    fc2bS= sm + KF_FC2B;
    float*    fcebS= sm + KF_FCEB;
    float*    wcS  = sm + KF_WC;

    const uint32_t as_b = smem_u32(sm);

    const int t = threadIdx.x;
    const int wid = t >> 5, lane = t & 31;
    const int gr = lane >> 2, tg = lane & 3;
    const int lr8 = (lane >> 3) & 1, l7 = lane & 7, lhi = lane >> 4;
    const int n0g = blockIdx.x * 64;
    const int b   = blockIdx.y;
    const int row0g = b * N_WRD + n0g;

    // ---- consts + wcode rows ----
    fc2bS[t] = fc2_b[t];
    if (t < 32) fcebS[t] = fce_b[t];
    if (t < 192) wcS[t] = g_wcode[row0g * 3 + t];
    __syncthreads();

    // ---- fc1 -> As fp16 ([64 rows][264 halves], word stride 132) ----
    {
        int r = t >> 2, kb = (t & 3) * 64;
        float w0 = wcS[r * 3 + 0], w1 = wcS[r * 3 + 1], w2 = wcS[r * 3 + 2];
        for (int k = kb; k < kb + 64; k += 4) {
            float a0 = fmaxf(fmaf(w0, fc1_w[k+0], fmaf(w1, fc1_w[256+k+0], fmaf(w2, fc1_w[512+k+0], fc1_b[k+0]))), 0.f);
            float a1 = fmaxf(fmaf(w0, fc1_w[k+1], fmaf(w1, fc1_w[256+k+1], fmaf(w2, fc1_w[512+k+1], fc1_b[k+1]))), 0.f);
            float a2 = fmaxf(fmaf(w0, fc1_w[k+2], fmaf(w1, fc1_w[256+k+2], fmaf(w2, fc1_w[512+k+2], fc1_b[k+2]))), 0.f);
            float a3 = fmaxf(fmaf(w0, fc1_w[k+3], fmaf(w1, fc1_w[256+k+3], fmaf(w2, fc1_w[512+k+3], fc1_b[k+3]))), 0.f);
            uint2 u; u.x = pack_h2(a0, a1); u.y = pack_h2(a2, a3);
            *(uint2*)&AsU[r * 132 + (k >> 1)] = u;
        }
    }
    __syncthreads();

    // ---- MMA1 (fp16): H2raw = A @ W2 (64x256, K=256). warps 2m x 4n --------
    const int wm = wid & 1, wn = wid >> 1;
    const int m0 = wm * 32, n0 = wn * 64;
    {
        const uint32_t* w2p = g_w2f16 + (wn * 8) * 64 + lane * 2;
        uint2 curB[8], nxtB[8];
#pragma unroll
        for (int j = 0; j < 8; j++) curB[j] = *(const uint2*)(w2p + j * 64);
        float acc1[2][8][4] = {};
        for (int k16 = 0; k16 < 16; k16++) {
            if (k16 < 15) {
                const uint32_t* p = w2p + (k16 + 1) * 2048;
#pragma unroll
                for (int j = 0; j < 8; j++) nxtB[j] = *(const uint2*)(p + j * 64);
            }
            uint32_t aF[2][4];
#pragma unroll
            for (int mt = 0; mt < 2; mt++) {
                uint32_t adr = as_b + (uint32_t)((m0 + mt * 16 + lr8 * 8 + l7) * 528
                                                  + k16 * 32 + lhi * 16);
                ldm_x4(aF[mt], adr);
            }
#pragma unroll
            for (int j = 0; j < 8; j++)
#pragma unroll
                for (int mt = 0; mt < 2; mt++)
                    mma16(acc1[mt][j], aF[mt], (const uint32_t*)&curB[j]);
#pragma unroll
            for (int j = 0; j < 8; j++) curB[j] = nxtB[j];
        }
        __syncthreads();   // all MMA1 reads of As done

        // epilogue1: H2 = relu(acc + bias) -> As fp16 (same region)
#pragma unroll
        for (int mt = 0; mt < 2; mt++) {
#pragma unroll
            for (int nt = 0; nt < 8; nt++) {
                int col = n0 + nt * 8 + 2 * tg;
                int r0 = m0 + mt * 16 + gr;
                float b0 = fc2bS[col], b1 = fc2bS[col + 1];
                float* d = acc1[mt][nt];
                AsU[r0 * 132 + (col >> 1)] =
                    pack_h2(fmaxf(d[0] + b0, 0.f), fmaxf(d[1] + b1, 0.f));
                AsU[(r0 + 8) * 132 + (col >> 1)] =
                    pack_h2(fmaxf(d[2] + b0, 0.f), fmaxf(d[3] + b1, 0.f));
            }
        }
    }
    __syncthreads();

    // ---- MMA2 (fp16): D2 = H2 @ We2 (64x64, K=256) -------------------------
    const int j0 = wn * 16;
    float acc2[2][2][4] = {};
    {
        const uint32_t* wep = g_we2f16 + (wn * 2) * 64 + lane * 2;
        uint2 curW[2], nxtW[2];
#pragma unroll
        for (int jj = 0; jj < 2; jj++) curW[jj] = *(const uint2*)(wep + jj * 64);
        for (int k16 = 0; k16 < 16; k16++) {
            if (k16 < 15) {
                const uint32_t* p = wep + (k16 + 1) * 512;
#pragma unroll
                for (int jj = 0; jj < 2; jj++) nxtW[jj] = *(const uint2*)(p + jj * 64);
            }
            uint32_t aF[2][4];
#pragma unroll
            for (int mt = 0; mt < 2; mt++) {
                uint32_t adr = as_b + (uint32_t)((m0 + mt * 16 + lr8 * 8 + l7) * 528
                                                  + k16 * 32 + lhi * 16);
                ldm_x4(aF[mt], adr);
            }
#pragma unroll
            for (int jj = 0; jj < 2; jj++)
#pragma unroll
                for (int mt = 0; mt < 2; mt++)
                    mma16(acc2[mt][jj], aF[mt], (const uint32_t*)&curW[jj]);
#pragma unroll
            for (int jj = 0; jj < 2; jj++) curW[jj] = nxtW[jj];
        }
    }
    __syncthreads();   // H2 reads done; As region reused for es

    // ---- epilogue2: es fp16 ([64][40 halves], word stride 20) + act --------
    {
        const float fcab = fca_b[0];
#pragma unroll
        for (int mt = 0; mt < 2; mt++) {
            int r0 = m0 + mt * 16 + gr;
#pragma unroll
            for (int jj = 0; jj < 2; jj++) {
                int col = j0 + jj * 8 + 2 * tg;
                float* d = acc2[mt][jj];
                if (col < 32) {
                    float b0 = fcebS[col], b1 = fcebS[col + 1];
                    AsU[r0 * 20 + (col >> 1)]       = pack_h2(d[0] + b0, d[1] + b1);
                    AsU[(r0 + 8) * 20 + (col >> 1)] = pack_h2(d[2] + b0, d[3] + b1);
                } else if (col == 32) {
                    actS[r0]     = sigmoidf_(d[0] + fcab);
                    actS[r0 + 8] = sigmoidf_(d[2] + fcab);
                }
            }
        }
    }
    __syncthreads();

    // ---- relation (fp16): M=64 n, N=256 v, K=32 ----------------------------
    const int v0 = wn * 64;
    float accr[2][8][4] = {};
    {
        const uint32_t* vsp = g_vsf16 + (wn * 8) * 64 + lane * 2;
        uint2 curV[8], nxtV[8];
#pragma unroll
        for (int j = 0; j < 8; j++) curV[j] = *(const uint2*)(vsp + j * 64);
#pragma unroll
        for (int e16 = 0; e16 < 2; e16++) {
            if (e16 < 1) {
                const uint32_t* p = vsp + 2048;
#pragma unroll
                for (int j = 0; j < 8; j++) nxtV[j] = *(const uint2*)(p + j * 64);
            }
            uint32_t aF[2][4];
#pragma unroll
            for (int mt = 0; mt < 2; mt++) {
                uint32_t adr = as_b + (uint32_t)((m0 + mt * 16 + lr8 * 8 + l7) * 80
                                                  + e16 * 32 + lhi * 16);
                ldm_x4(aF[mt], adr);
            }
#pragma unroll
            for (int j = 0; j < 8; j++)
#pragma unroll
                for (int mt = 0; mt < 2; mt++)
                    mma16(accr[mt][j], aF[mt], (const uint32_t*)&curV[j]);
#pragma unroll
            for (int j = 0; j < 8; j++) curV[j] = nxtV[j];
        }
    }

    // ---- softmax (registers + small smem combines) -------------------------
#pragma unroll
    for (int mt = 0; mt < 2; mt++) {
        float mxa = -1e30f, mxb = -1e30f;
#pragma unroll
        for (int nt = 0; nt < 8; nt++) {
            float* d = accr[mt][nt];
            mxa = fmaxf(mxa, fmaxf(d[0], d[1]));
            mxb = fmaxf(mxb, fmaxf(d[2], d[3]));
        }
        mxa = fmaxf(mxa, __shfl_xor_sync(0xffffffffu, mxa, 1));
        mxa = fmaxf(mxa, __shfl_xor_sync(0xffffffffu, mxa, 2));
        mxb = fmaxf(mxb, __shfl_xor_sync(0xffffffffu, mxb, 1));
        mxb = fmaxf(mxb, __shfl_xor_sync(0xffffffffu, mxb, 2));
        if (tg == 0) {
            redm[(m0 + mt * 16 + gr) * 4 + wn] = mxa;
            redm[(m0 + mt * 16 + 8 + gr) * 4 + wn] = mxb;
        }
    }
    __syncthreads();   // es reads complete; redm visible

#pragma unroll
    for (int mt = 0; mt < 2; mt++) {
        int na = m0 + mt * 16 + gr, nb = na + 8;
        float ma = fmaxf(fmaxf(redm[na * 4 + 0], redm[na * 4 + 1]),
                         fmaxf(redm[na * 4 + 2], redm[na * 4 + 3]));
        float mb = fmaxf(fmaxf(redm[nb * 4 + 0], redm[nb * 4 + 1]),
                         fmaxf(redm[nb * 4 + 2], redm[nb * 4 + 3]));
        float sa = 0.f, sb = 0.f;
#pragma unroll
        for (int nt = 0; nt < 8; nt++) {
            float* d = accr[mt][nt];
            d[0] = __expf(d[0] - ma); d[1] = __expf(d[1] - ma);
            d[2] = __expf(d[2] - mb); d[3] = __expf(d[3] - mb);
            sa += d[0] + d[1];
            sb += d[2] + d[3];
        }
        sa += __shfl_xor_sync(0xffffffffu, sa, 1);
        sa += __shfl_xor_sync(0xffffffffu, sa, 2);
        sb += __shfl_xor_sync(0xffffffffu, sb, 1);
        sb += __shfl_xor_sync(0xffffffffu, sb, 2);
        if (tg == 0) { reds[na * 4 + wn] = sa; reds[nb * 4 + wn] = sb; }
    }
    __syncthreads();

    // scale + write route fp16 [64 n][264 halves] (word stride 132) ----------
#pragma unroll
    for (int mt = 0; mt < 2; mt++) {
        int na = m0 + mt * 16 + gr, nb = na + 8;
        float sA = reds[na * 4 + 0] + reds[na * 4 + 1] + reds[na * 4 + 2] + reds[na * 4 + 3];
        float sB = reds[nb * 4 + 0] + reds[nb * 4 + 1] + reds[nb * 4 + 2] + reds[nb * 4 + 3];
        float scA = actS[na] / sA;
        float scB = actS[nb] / sB;
#pragma unroll
        for (int nt = 0; nt < 8; nt++) {
            int v = v0 + nt * 8 + 2 * tg;
            float* d = accr[mt][nt];
            AsU[na * 132 + (v >> 1)] = pack_h2(d[0] * scA, d[1] * scA);
            AsU[nb * 132 + (v >> 1)] = pack_h2(d[2] * scB, d[3] * scB);
        }
    }
    __syncthreads();

    // ---- out GEMM (fp16): out[c][n] = VC @ route, M=128, N=64, K=256 -------
    const int wm2 = wid >> 1, wn2 = wid & 1;
    const int c0 = wm2 * 32, n0o = wn2 * 32;
    float acco[2][4][4] = {};
    {
        const uint32_t* vcp = g_vcf16 + ((size_t)(b * 16) * 8 + wm2 * 2) * 128 + lane * 4;
        uint4 curA[2], nxtA[2];
#pragma unroll
        for (int mt = 0; mt < 2; mt++) curA[mt] = *(const uint4*)(vcp + mt * 128);
        for (int v16 = 0; v16 < 16; v16++) {
            if (v16 < 15) {
                const uint32_t* p = vcp + (size_t)(v16 + 1) * 1024;
#pragma unroll
                for (int mt = 0; mt < 2; mt++) nxtA[mt] = *(const uint4*)(p + mt * 128);
            }
#pragma unroll
            for (int ntp = 0; ntp < 2; ntp++) {
                uint32_t bF[4];
                uint32_t adr = as_b + (uint32_t)((n0o + ntp * 16 + lhi * 8 + l7) * 528
                                                  + v16 * 32 + lr8 * 16);
                ldm_x4(bF, adr);
#pragma unroll
                for (int mt = 0; mt < 2; mt++) {
                    mma16(acco[mt][2 * ntp],     (const uint32_t*)&curA[mt], bF);
                    mma16(acco[mt][2 * ntp + 1], (const uint32_t*)&curA[mt], bF + 2);
                }
            }
#pragma unroll
            for (int mt = 0; mt < 2; mt++) curA[mt] = nxtA[mt];
        }
    }

    // ---- store out (acco[mt][2*ntp + oct]: n-octet = ntp*16 + oct*8) -------
#pragma unroll
    for (int mt = 0; mt < 2; mt++) {
#pragma unroll
        for (int nt = 0; nt < 4; nt++) {
            int r0 = c0 + mt * 16 + gr;
            int ng = n0g + n0o + (nt >> 1) * 16 + (nt & 1) * 8 + 2 * tg;
            float* d = acco[mt][nt];
            if (ng < N_WRD) {
                float2 s0; s0.x = d[0]; s0.y = d[1];
                float2 s1; s1.x = d[2]; s1.y = d[3];
                *(float2*)&out[((size_t)b * CSZ + r0) * N_WRD + ng]     = s0;
                *(float2*)&out[((size_t)b * CSZ + r0 + 8) * N_WRD + ng] = s1;
            }
        }
    }
}

// ---------------- launch --------------------------------------------------
extern "C" void kernel_launch(void* const* d_in, const int* in_sizes, int n_in,
                              void* d_out, int out_size) {
    const float* view_cell = (const float*)d_in[0];
    const float* v         = (const float*)d_in[1];
    const float* w2c_w1    = (const float*)d_in[2];
    const float* w2c_b1    = (const float*)d_in[3];
    const float* w2c_w2    = (const float*)d_in[4];
    const float* w2c_b2    = (const float*)d_in[5];
    const float* fc1_w     = (const float*)d_in[6];
    const float* fc1_b     = (const float*)d_in[7];
    const float* fc2_w     = (const float*)d_in[8];
    const float* fc2_b     = (const float*)d_in[9];
    const float* fca_w     = (const float*)d_in[10];
    const float* fca_b     = (const float*)d_in[11];
    const float* fce_w     = (const float*)d_in[12];
    const float* fce_b     = (const float*)d_in[13];
    const float* vse_w1    = (const float*)d_in[14];
    const float* vse_b1    = (const float*)d_in[15];
    const float* vse_w2    = (const float*)d_in[16];
    const float* vse_b2    = (const float*)d_in[17];
    float* out = (float*)d_out;

    static bool attr_set = false;
    if (!attr_set) {
        cudaFuncSetAttribute(k_AB, cudaFuncAttributeMaxDynamicSharedMemorySize, KF_TOT * 4);
        attr_set = true;
    }

    k_setup<<<1294, 256>>>(fc2_w, fce_w, fca_w, view_cell, v, w2c_w1, w2c_b1,
                           w2c_w2, w2c_b2, vse_w1, vse_b1, vse_w2, vse_b2);
    dim3 gridF((N_WRD + 63) / 64, B_SZ);
    k_AB<<<gridF, 256, KF_TOT * 4>>>(fc1_w, fc1_b, fc2_b, fca_b, fce_b, out);
}

// round 13
// speedup vs baseline: 2.1849x; 1.1761x over previous
#include <cuda_runtime.h>
#include <cuda_fp16.h>
#include <cstdint>

#define N_WRD  2000
#define B_SZ   64
#define CSZ    128
#define V_PIX  256
#define EMB    32

// ---------------- scratch (device globals; no allocations allowed) ----------
__device__ float    g_wcode[B_SZ * 6000 + 192];            // padded for tile overrun
__device__ uint32_t g_w2f16[16 * 32 * 64];                 // W2 fp16 B-frags [k16][n8][64]
__device__ uint32_t g_we2f16[16 * 8 * 64];                 // We2 fp16 B-frags [k16][j8][64]
__device__ uint32_t g_vsf16[2 * 32 * 64];                  // vs fp16 B-frags [e16][v8][64]
__device__ uint32_t g_vcf16[(size_t)B_SZ * 16 * 8 * 128];  // VC fp16 A-frags [b][v16][c16][128]
__device__ float4   g_f1p[256];                            // fc1 frag-packed [k16][tg][kq]

// ============================ helpers =======================================
__device__ __forceinline__ uint32_t pack_h2(float lo, float hi) {
    __half2 h = __floats2half2_rn(lo, hi);
    return *(uint32_t*)&h;
}
__device__ __forceinline__ void mma16(float* d, const uint32_t* a, const uint32_t* b) {
    asm volatile("mma.sync.aligned.m16n8k16.row.col.f32.f16.f16.f32 "
        "{%0,%1,%2,%3}, {%4,%5,%6,%7}, {%8,%9}, {%0,%1,%2,%3};"
        : "+f"(d[0]), "+f"(d[1]), "+f"(d[2]), "+f"(d[3])
        : "r"(a[0]), "r"(a[1]), "r"(a[2]), "r"(a[3]), "r"(b[0]), "r"(b[1]));
}
__device__ __forceinline__ void ldm_x4(uint32_t* r, uint32_t addr) {
    asm volatile("ldmatrix.sync.aligned.m8n8.x4.shared.b16 {%0,%1,%2,%3}, [%4];"
        : "=r"(r[0]), "=r"(r[1]), "=r"(r[2]), "=r"(r[3]) : "r"(addr));
}
__device__ __forceinline__ uint32_t smem_u32(const void* p) {
    uint32_t a;
    asm("{ .reg .u64 t; cvta.to.shared.u64 t, %1; cvt.u32.u64 %0, t; }"
        : "=r"(a) : "l"(p));
    return a;
}
__device__ __forceinline__ float sigmoidf_(float x) {
    return 1.f / (1.f + __expf(-x));
}
__device__ __forceinline__ float dot3(const float* wc, float4 q) {
    return fmaf(wc[0], q.x, fmaf(wc[1], q.y, fmaf(wc[2], q.z, q.w)));
}

// ====== setup kernel ========================================================
// blocks: [0,128) w2f16 | [128,160) we2f16 | [160,176) vsf16 | [176,1200) vcf16
//         [1200,1294) wcode | [1294] f1p
__global__ __launch_bounds__(256) void k_setup(
    const float* __restrict__ fc2_w, const float* __restrict__ fce_w,
    const float* __restrict__ fca_w, const float* __restrict__ vc_g,
    const float* __restrict__ v, const float* __restrict__ w2c_w1,
    const float* __restrict__ w2c_b1,
    const float* __restrict__ w2c_w2, const float* __restrict__ w2c_b2,
    const float* __restrict__ fc1_w, const float* __restrict__ fc1_b,
    const float* __restrict__ vse_w1, const float* __restrict__ vse_b1,
    const float* __restrict__ vse_w2, const float* __restrict__ vse_b2) {
    const int bid = blockIdx.x;
    const int t = threadIdx.x;
    if (bid < 128) {
        int idx = bid * 256 + t;
        int k16 = idx >> 11, rem = idx & 2047;
        int n8 = rem >> 6, w = rem & 63;
        int lane = w >> 1, h = w & 1;
        int k0 = k16 * 16 + (lane & 3) * 2 + h * 8;
        int n  = n8 * 8 + (lane >> 2);
        g_w2f16[idx] = pack_h2(fc2_w[k0 * 256 + n], fc2_w[(k0 + 1) * 256 + n]);
    } else if (bid < 160) {
        int idx = (bid - 128) * 256 + t;
        int k16 = idx >> 9, rem = idx & 511;
        int j8 = rem >> 6, w = rem & 63;
        int lane = w >> 1, h = w & 1;
        int k0 = k16 * 16 + (lane & 3) * 2 + h * 8;
        int j = j8 * 8 + (lane >> 2);
        float v0 = (j < 32) ? fce_w[k0 * 32 + j] : ((j == 32) ? fca_w[k0] : 0.f);
        float v1 = (j < 32) ? fce_w[(k0 + 1) * 32 + j] : ((j == 32) ? fca_w[k0 + 1] : 0.f);
        g_we2f16[idx] = pack_h2(v0, v1);
    } else if (bid < 176) {
        int idx = (bid - 160) * 256 + t;
        int e16 = idx >> 11, rem = idx & 2047;
        int v8 = rem >> 6, w = rem & 63;
        int lane = w >> 1, h = w & 1;
        int vv = v8 * 8 + (lane >> 2);
        int e0 = e16 * 16 + (lane & 3) * 2 + h * 8;
        float x = -1.f + (2.f / 15.f) * (float)(vv >> 4);
        float y = -1.f + (2.f / 15.f) * (float)(vv & 15);
        float a0 = vse_b2[e0], a1 = vse_b2[e0 + 1];
#pragma unroll 4
        for (int j = 0; j < 128; j++) {
            float hh = fmaxf(fmaf(x, vse_w1[j], fmaf(y, vse_w1[128 + j], vse_b1[j])), 0.f);
            a0 = fmaf(hh, vse_w2[j * EMB + e0], a0);
            a1 = fmaf(hh, vse_w2[j * EMB + e0 + 1], a1);
        }
        g_vsf16[idx] = pack_h2(a0, a1);
    } else if (bid < 1200) {
        int blk = bid - 176;
        int b = blk >> 4, v16 = blk & 15;
        for (int i = t; i < 1024; i += 256) {
            int c16 = i >> 7, w = i & 127;
            int lane = w >> 2, q = w & 3;
            int c = c16 * 16 + (lane >> 2) + (q & 1) * 8;
            int v0 = v16 * 16 + 2 * (lane & 3) + (q >> 1) * 8;
            const float* src = &vc_g[((size_t)b * CSZ + c) * V_PIX + v0];
            g_vcf16[((size_t)(b * 16 + v16) * 8 + c16) * 128 + w] =
                pack_h2(src[0], src[1]);
        }
    } else if (bid < 1294) {
        // ---- wcode tile ----
        __shared__ float As[64 * 33];
        __shared__ float Bs[32 * 68];
        __shared__ float vS[448];
        int tx = t & 15, ty = t >> 4;
        int n0 = (bid - 1200) * 64;
        for (int i = t; i < 448; i += 256) vS[i] = v[i];
        __syncthreads();
        float acc[4][4] = {};
        for (int k0 = 0; k0 < 512; k0 += 32) {
            for (int i = t; i < 2048; i += 256) {
                int r = i >> 5, k = i & 31;
                int kk = k0 + k;
                float a = w2c_b1[kk];
#pragma unroll
                for (int q = 0; q < 7; q++)
                    a = fmaf(vS[r * 7 + q], w2c_w1[q * 512 + kk], a);
                As[r * 33 + k] = fmaxf(a, 0.f);
            }
            for (int i = t; i < 2048; i += 256) {
                int k = i >> 6, n = i & 63;
                int nn = n0 + n;
                Bs[k * 68 + n] = (nn < 6000) ? w2c_w2[(k0 + k) * 6000 + nn] : 0.f;
            }
            __syncthreads();
#pragma unroll
            for (int k = 0; k < 32; k++) {
                float a[4], bb[4];
#pragma unroll
                for (int i = 0; i < 4; i++) a[i] = As[(4 * ty + i) * 33 + k];
#pragma unroll
                for (int j = 0; j < 4; j++) bb[j] = Bs[k * 68 + 4 * tx + j];
#pragma unroll
                for (int i = 0; i < 4; i++)
#pragma unroll
                    for (int j = 0; j < 4; j++) acc[i][j] = fmaf(a[i], bb[j], acc[i][j]);
            }
            __syncthreads();
        }
#pragma unroll
        for (int i = 0; i < 4; i++) {
            int r = 4 * ty + i;
#pragma unroll
            for (int j = 0; j < 4; j++) {
                int col = n0 + 4 * tx + j;
                if (col < 6000) g_wcode[r * 6000 + col] = acc[i][j] + w2c_b2[col];
            }
        }
    } else {
        // f1p: [k16][tg][kq] -> (fc1_w[k], fc1_w[256+k], fc1_w[512+k], fc1_b[k])
        int k16 = t >> 4, tg = (t >> 2) & 3, kq = t & 3;
        int k = k16 * 16 + 2 * tg + (kq & 1) + (kq >> 1) * 8;
        float4 q;
        q.x = fc1_w[k]; q.y = fc1_w[256 + k]; q.z = fc1_w[512 + k]; q.w = fc1_b[k];
        g_f1p[t] = q;
    }
}

// ====== fused kernel ========================================================
// smem words: As region [0,8448): H2 fp16 [64][264 halves], es fp16 [64][40h],
//             route fp16 [64][264 halves] (phase-disjoint)
#define KF_AS    0
#define KF_ACT   8448       // 64
#define KF_RM    8512       // 256
#define KF_RS    8768       // 256
#define KF_FC2B  9024       // 256
#define KF_FCEB  9280       // 32
#define KF_WC    9312       // 192
#define KF_TOT   9504       // -> 38016 bytes

__global__ __launch_bounds__(256, 2) void k_AB(
    const float* __restrict__ fc2_b,
    const float* __restrict__ fca_b, const float* __restrict__ fce_b,
    float* __restrict__ out) {
    extern __shared__ float sm[];
    uint32_t* AsU  = (uint32_t*)sm;
    float*    actS = sm + KF_ACT;
    float*    redm = sm + KF_RM;
    float*    reds = sm + KF_RS;
    float*    fc2bS= sm + KF_FC2B;
    float*    fcebS= sm + KF_FCEB;
    float*    wcS  = sm + KF_WC;

    const uint32_t as_b = smem_u32(sm);

    const int t = threadIdx.x;
    const int wid = t >> 5, lane = t & 31;
    const int gr = lane >> 2, tg = lane & 3;
    const int lr8 = (lane >> 3) & 1, l7 = lane & 7, lhi = lane >> 4;
    const int n0g = blockIdx.x * 64;
    const int b   = blockIdx.y;
    const int row0g = b * N_WRD + n0g;

    // ---- consts + wcode rows ----
    fc2bS[t] = fc2_b[t];
    if (t < 32) fcebS[t] = fce_b[t];
    if (t < 192) wcS[t] = g_wcode[row0g * 3 + t];
    __syncthreads();

    // ---- MMA1 (fp16): H2raw = A @ W2 (64x256, K=256). warps 2m x 4n --------
    // A-operand computed per-thread in fragment registers (fc1 = 3 FMAs/elem).
    const int wm = wid & 1, wn = wid >> 1;
    const int m0 = wm * 32, n0 = wn * 64;
    {
        // per-thread wcode for the 4 rows this thread's A-frags touch
        float wcr[4][3];
#pragma unroll
        for (int rr = 0; rr < 4; rr++) {
            int r = m0 + gr + rr * 8;
            wcr[rr][0] = wcS[r * 3 + 0];
            wcr[rr][1] = wcS[r * 3 + 1];
            wcr[rr][2] = wcS[r * 3 + 2];
        }
        const uint32_t* w2p = g_w2f16 + (wn * 8) * 64 + lane * 2;
        const float4* f1t = g_f1p + tg * 4;
        float acc1[2][8][4] = {};
        for (int k16 = 0; k16 < 16; k16++) {
            uint2 curB[8];
            const uint32_t* p = w2p + k16 * 2048;
#pragma unroll
            for (int j = 0; j < 8; j++) curB[j] = *(const uint2*)(p + j * 64);
            const float4* fp = f1t + k16 * 16;
            float4 q0 = fp[0], q1 = fp[1], q2 = fp[2], q3 = fp[3];
            uint32_t aF[2][4];
#pragma unroll
            for (int mt = 0; mt < 2; mt++) {
                const float* w0 = wcr[2 * mt];
                const float* w1 = wcr[2 * mt + 1];
                aF[mt][0] = pack_h2(fmaxf(dot3(w0, q0), 0.f), fmaxf(dot3(w0, q1), 0.f));
                aF[mt][1] = pack_h2(fmaxf(dot3(w1, q0), 0.f), fmaxf(dot3(w1, q1), 0.f));
                aF[mt][2] = pack_h2(fmaxf(dot3(w0, q2), 0.f), fmaxf(dot3(w0, q3), 0.f));
                aF[mt][3] = pack_h2(fmaxf(dot3(w1, q2), 0.f), fmaxf(dot3(w1, q3), 0.f));
            }
#pragma unroll
            for (int j = 0; j < 8; j++)
#pragma unroll
                for (int mt = 0; mt < 2; mt++)
                    mma16(acc1[mt][j], aF[mt], (const uint32_t*)&curB[j]);
        }
        // epilogue1: H2 = relu(acc + bias) -> As fp16 [64][264 halves]
#pragma unroll
        for (int mt = 0; mt < 2; mt++) {
#pragma unroll
            for (int nt = 0; nt < 8; nt++) {
                int col = n0 + nt * 8 + 2 * tg;
                int r0 = m0 + mt * 16 + gr;
                float b0 = fc2bS[col], b1 = fc2bS[col + 1];
                float* d = acc1[mt][nt];
                AsU[r0 * 132 + (col >> 1)] =
                    pack_h2(fmaxf(d[0] + b0, 0.f), fmaxf(d[1] + b1, 0.f));
                AsU[(r0 + 8) * 132 + (col >> 1)] =
                    pack_h2(fmaxf(d[2] + b0, 0.f), fmaxf(d[3] + b1, 0.f));
            }
        }
    }
    __syncthreads();

    // ---- MMA2 (fp16): D2 = H2 @ We2 (64x64, K=256) -------------------------
    const int j0 = wn * 16;
    float acc2[2][2][4] = {};
    {
        const uint32_t* wep = g_we2f16 + (wn * 2) * 64 + lane * 2;
        uint2 curW[2], nxtW[2];
#pragma unroll
        for (int jj = 0; jj < 2; jj++) curW[jj] = *(const uint2*)(wep + jj * 64);
        for (int k16 = 0; k16 < 16; k16++) {
            if (k16 < 15) {
                const uint32_t* p = wep + (k16 + 1) * 512;
#pragma unroll
                for (int jj = 0; jj < 2; jj++) nxtW[jj] = *(const uint2*)(p + jj * 64);
            }
            uint32_t aF[2][4];
#pragma unroll
            for (int mt = 0; mt < 2; mt++) {
                uint32_t adr = as_b + (uint32_t)((m0 + mt * 16 + lr8 * 8 + l7) * 528
                                                  + k16 * 32 + lhi * 16);
                ldm_x4(aF[mt], adr);
            }
#pragma unroll
            for (int jj = 0; jj < 2; jj++)
#pragma unroll
                for (int mt = 0; mt < 2; mt++)
                    mma16(acc2[mt][jj], aF[mt], (const uint32_t*)&curW[jj]);
#pragma unroll
            for (int jj = 0; jj < 2; jj++) curW[jj] = nxtW[jj];
        }
    }
    __syncthreads();   // H2 reads done; As region reused for es

    // ---- epilogue2: es fp16 ([64][40 halves], word stride 20) + act --------
    {
        const float fcab = fca_b[0];
#pragma unroll
        for (int mt = 0; mt < 2; mt++) {
            int r0 = m0 + mt * 16 + gr;
#pragma unroll
            for (int jj = 0; jj < 2; jj++) {
                int col = j0 + jj * 8 + 2 * tg;
                float* d = acc2[mt][jj];
                if (col < 32) {
                    float b0 = fcebS[col], b1 = fcebS[col + 1];
                    AsU[r0 * 20 + (col >> 1)]       = pack_h2(d[0] + b0, d[1] + b1);
                    AsU[(r0 + 8) * 20 + (col >> 1)] = pack_h2(d[2] + b0, d[3] + b1);
                } else if (col == 32) {
                    actS[r0]     = sigmoidf_(d[0] + fcab);
                    actS[r0 + 8] = sigmoidf_(d[2] + fcab);
                }
            }
        }
    }
    __syncthreads();

    // ---- relation (fp16): M=64 n, N=256 v, K=32 ----------------------------
    const int v0 = wn * 64;
    float accr[2][8][4] = {};
    {
        const uint32_t* vsp = g_vsf16 + (wn * 8) * 64 + lane * 2;
        uint2 curV[8], nxtV[8];
#pragma unroll
        for (int j = 0; j < 8; j++) curV[j] = *(const uint2*)(vsp + j * 64);
#pragma unroll
        for (int e16 = 0; e16 < 2; e16++) {
            if (e16 < 1) {
                const uint32_t* p = vsp + 2048;
#pragma unroll
                for (int j = 0; j < 8; j++) nxtV[j] = *(const uint2*)(p + j * 64);
            }
            uint32_t aF[2][4];
#pragma unroll
            for (int mt = 0; mt < 2; mt++) {
                uint32_t adr = as_b + (uint32_t)((m0 + mt * 16 + lr8 * 8 + l7) * 80
                                                  + e16 * 32 + lhi * 16);
                ldm_x4(aF[mt], adr);
            }
#pragma unroll
            for (int j = 0; j < 8; j++)
#pragma unroll
                for (int mt = 0; mt < 2; mt++)
                    mma16(accr[mt][j], aF[mt], (const uint32_t*)&curV[j]);
#pragma unroll
            for (int j = 0; j < 8; j++) curV[j] = nxtV[j];
        }
    }

    // ---- softmax (registers + small smem combines) -------------------------
#pragma unroll
    for (int mt = 0; mt < 2; mt++) {
        float mxa = -1e30f, mxb = -1e30f;
#pragma unroll
        for (int nt = 0; nt < 8; nt++) {
            float* d = accr[mt][nt];
            mxa = fmaxf(mxa, fmaxf(d[0], d[1]));
            mxb = fmaxf(mxb, fmaxf(d[2], d[3]));
        }
        mxa = fmaxf(mxa, __shfl_xor_sync(0xffffffffu, mxa, 1));
        mxa = fmaxf(mxa, __shfl_xor_sync(0xffffffffu, mxa, 2));
        mxb = fmaxf(mxb, __shfl_xor_sync(0xffffffffu, mxb, 1));
        mxb = fmaxf(mxb, __shfl_xor_sync(0xffffffffu, mxb, 2));
        if (tg == 0) {
            redm[(m0 + mt * 16 + gr) * 4 + wn] = mxa;
            redm[(m0 + mt * 16 + 8 + gr) * 4 + wn] = mxb;
        }
    }
    __syncthreads();   // es reads complete; redm visible

#pragma unroll
    for (int mt = 0; mt < 2; mt++) {
        int na = m0 + mt * 16 + gr, nb = na + 8;
        float ma = fmaxf(fmaxf(redm[na * 4 + 0], redm[na * 4 + 1]),
                         fmaxf(redm[na * 4 + 2], redm[na * 4 + 3]));
        float mb = fmaxf(fmaxf(redm[nb * 4 + 0], redm[nb * 4 + 1]),
                         fmaxf(redm[nb * 4 + 2], redm[nb * 4 + 3]));
        float sa = 0.f, sb = 0.f;
#pragma unroll
        for (int nt = 0; nt < 8; nt++) {
            float* d = accr[mt][nt];
            d[0] = __expf(d[0] - ma); d[1] = __expf(d[1] - ma);
            d[2] = __expf(d[2] - mb); d[3] = __expf(d[3] - mb);
            sa += d[0] + d[1];
            sb += d[2] + d[3];
        }
        sa += __shfl_xor_sync(0xffffffffu, sa, 1);
        sa += __shfl_xor_sync(0xffffffffu, sa, 2);
        sb += __shfl_xor_sync(0xffffffffu, sb, 1);
        sb += __shfl_xor_sync(0xffffffffu, sb, 2);
        if (tg == 0) { reds[na * 4 + wn] = sa; reds[nb * 4 + wn] = sb; }
    }
    __syncthreads();

    // scale + write route fp16 [64 n][264 halves] (word stride 132) ----------
#pragma unroll
    for (int mt = 0; mt < 2; mt++) {
        int na = m0 + mt * 16 + gr, nb = na + 8;
        float sA = reds[na * 4 + 0] + reds[na * 4 + 1] + reds[na * 4 + 2] + reds[na * 4 + 3];
        float sB = reds[nb * 4 + 0] + reds[nb * 4 + 1] + reds[nb * 4 + 2] + reds[nb * 4 + 3];
        float scA = actS[na] / sA;
        float scB = actS[nb] / sB;
#pragma unroll
        for (int nt = 0; nt < 8; nt++) {
            int v = v0 + nt * 8 + 2 * tg;
            float* d = accr[mt][nt];
            AsU[na * 132 + (v >> 1)] = pack_h2(d[0] * scA, d[1] * scA);
            AsU[nb * 132 + (v >> 1)] = pack_h2(d[2] * scB, d[3] * scB);
        }
    }
    __syncthreads();

    // ---- out GEMM (fp16): out[c][n] = VC @ route, M=128, N=64, K=256 -------
    const int wm2 = wid >> 1, wn2 = wid & 1;
    const int c0 = wm2 * 32, n0o = wn2 * 32;
    float acco[2][4][4] = {};
    {
        const uint32_t* vcp = g_vcf16 + ((size_t)(b * 16) * 8 + wm2 * 2) * 128 + lane * 4;
        uint4 curA[2], nxtA[2];
#pragma unroll
        for (int mt = 0; mt < 2; mt++) curA[mt] = *(const uint4*)(vcp + mt * 128);
        for (int v16 = 0; v16 < 16; v16++) {
            if (v16 < 15) {
                const uint32_t* p = vcp + (size_t)(v16 + 1) * 1024;
#pragma unroll
                for (int mt = 0; mt < 2; mt++) nxtA[mt] = *(const uint4*)(p + mt * 128);
            }
#pragma unroll
            for (int ntp = 0; ntp < 2; ntp++) {
                uint32_t bF[4];
                uint32_t adr = as_b + (uint32_t)((n0o + ntp * 16 + lhi * 8 + l7) * 528
                                                  + v16 * 32 + lr8 * 16);
                ldm_x4(bF, adr);
#pragma unroll
                for (int mt = 0; mt < 2; mt++) {
                    mma16(acco[mt][2 * ntp],     (const uint32_t*)&curA[mt], bF);
                    mma16(acco[mt][2 * ntp + 1], (const uint32_t*)&curA[mt], bF + 2);
                }
            }
#pragma unroll
            for (int mt = 0; mt < 2; mt++) curA[mt] = nxtA[mt];
        }
    }

    // ---- store out (acco[mt][2*ntp + oct]: n-octet = ntp*16 + oct*8) -------
#pragma unroll
    for (int mt = 0; mt < 2; mt++) {
#pragma unroll
        for (int nt = 0; nt < 4; nt++) {
            int r0 = c0 + mt * 16 + gr;
            int ng = n0g + n0o + (nt >> 1) * 16 + (nt & 1) * 8 + 2 * tg;
            float* d = acco[mt][nt];
            if (ng < N_WRD) {
                float2 s0; s0.x = d[0]; s0.y = d[1];
                float2 s1; s1.x = d[2]; s1.y = d[3];
                *(float2*)&out[((size_t)b * CSZ + r0) * N_WRD + ng]     = s0;
                *(float2*)&out[((size_t)b * CSZ + r0 + 8) * N_WRD + ng] = s1;
            }
        }
    }
}

// ---------------- launch --------------------------------------------------
extern "C" void kernel_launch(void* const* d_in, const int* in_sizes, int n_in,
                              void* d_out, int out_size) {
    const float* view_cell = (const float*)d_in[0];
    const float* v         = (const float*)d_in[1];
    const float* w2c_w1    = (const float*)d_in[2];
    const float* w2c_b1    = (const float*)d_in[3];
    const float* w2c_w2    = (const float*)d_in[4];
    const float* w2c_b2    = (const float*)d_in[5];
    const float* fc1_w     = (const float*)d_in[6];
    const float* fc1_b     = (const float*)d_in[7];
    const float* fc2_w     = (const float*)d_in[8];
    const float* fc2_b     = (const float*)d_in[9];
    const float* fca_w     = (const float*)d_in[10];
    const float* fca_b     = (const float*)d_in[11];
    const float* fce_w     = (const float*)d_in[12];
    const float* fce_b     = (const float*)d_in[13];
    const float* vse_w1    = (const float*)d_in[14];
    const float* vse_b1    = (const float*)d_in[15];
    const float* vse_w2    = (const float*)d_in[16];
    const float* vse_b2    = (const float*)d_in[17];
    float* out = (float*)d_out;

    static bool attr_set = false;
    if (!attr_set) {
        cudaFuncSetAttribute(k_AB, cudaFuncAttributeMaxDynamicSharedMemorySize, KF_TOT * 4);
        attr_set = true;
    }

    k_setup<<<1295, 256>>>(fc2_w, fce_w, fca_w, view_cell, v, w2c_w1, w2c_b1,
                           w2c_w2, w2c_b2, fc1_w, fc1_b,
                           vse_w1, vse_b1, vse_w2, vse_b2);
    dim3 gridF((N_WRD + 63) / 64, B_SZ);
    k_AB<<<gridF, 256, KF_TOT * 4>>>(fc2_b, fca_b, fce_b, out);
}